// round 1
// baseline (speedup 1.0000x reference)
#include <cuda_runtime.h>

// Problem constants
#define Bb 4
#define Tt 2048
#define Cc 1024
#define Hh 16
#define Dd 64
#define Mm (Bb * Tt)       // 8192 rows
#define N_QKV (3 * Cc)     // 3072
#define NW_QKV (N_QKV * Cc)    // 3,145,728
#define NW_OUT (Cc * Cc)       // 1,048,576

// -------------------- device scratch (no allocations allowed) --------------------
__device__ float g_partial[1024];
__device__ float g_scale_inv;                  // 1/scale for current weight tensor
__device__ float g_wq[NW_QKV];                 // ternary qkv weights (fp32 {-1,0,1})
__device__ float g_wo[NW_OUT];                 // ternary out-proj weights
__device__ float g_q[Bb * Hh * Tt * Dd];       // [B,H,T,D]
__device__ float g_k[Bb * Hh * Tt * Dd];
__device__ float g_v[Bb * Hh * Tt * Dd];
__device__ float g_att[Mm * Cc];               // attention output, [B,T,C] row-major

// -------------------- absmean scale: deterministic 2-pass reduction --------------------
__global__ void abssum_partial_kernel(const float* __restrict__ w, int n) {
    __shared__ float sd[256];
    int chunk = (n + (int)gridDim.x - 1) / (int)gridDim.x;
    int start = (int)blockIdx.x * chunk;
    int end = start + chunk; if (end > n) end = n;
    float s = 0.f;
    for (int i = start + (int)threadIdx.x; i < end; i += 256) s += fabsf(w[i]);
    sd[threadIdx.x] = s;
    __syncthreads();
    for (int o = 128; o > 0; o >>= 1) {
        if ((int)threadIdx.x < o) sd[threadIdx.x] += sd[threadIdx.x + o];
        __syncthreads();
    }
    if (threadIdx.x == 0) g_partial[blockIdx.x] = sd[0];
}

__global__ void finalize_scale_kernel(float inv_n) {
    __shared__ float sd[256];
    float s = 0.f;
    for (int i = threadIdx.x; i < 1024; i += 256) s += g_partial[i];
    sd[threadIdx.x] = s;
    __syncthreads();
    for (int o = 128; o > 0; o >>= 1) {
        if ((int)threadIdx.x < o) sd[threadIdx.x] += sd[threadIdx.x + o];
        __syncthreads();
    }
    if (threadIdx.x == 0) {
        float sc = fmaxf(sd[0] * inv_n, 1e-8f);
        g_scale_inv = 1.0f / sc;
    }
}

// WHICH: 0 -> g_wq, 1 -> g_wo.  n4 = element count / 4
template <int WHICH>
__global__ void quantize_kernel(const float* __restrict__ w, int n4) {
    int i = (int)blockIdx.x * 256 + (int)threadIdx.x;
    if (i >= n4) return;
    float inv = g_scale_inv;
    float4 v = ((const float4*)w)[i];
    float4 r;
    r.x = fminf(1.f, fmaxf(-1.f, rintf(v.x * inv)));
    r.y = fminf(1.f, fmaxf(-1.f, rintf(v.y * inv)));
    r.z = fminf(1.f, fmaxf(-1.f, rintf(v.z * inv)));
    r.w = fminf(1.f, fmaxf(-1.f, rintf(v.w * inv)));
    float4* dst = (WHICH == 0) ? (float4*)g_wq : (float4*)g_wo;
    dst[i] = r;
}

// -------------------- tiled SGEMM: C[m][n] = sum_k A[m][k] * B[n][k] --------------------
// MODE 0: A = x (param), B = g_wq, scatter-epilogue into g_q/g_k/g_v ([B,H,T,D])
// MODE 1: A = g_att,     B = g_wo, C = out (param), plain row-major
template <int MODE>
__global__ __launch_bounds__(256) void sgemm_kernel(const float* __restrict__ Aparam,
                                                    float* __restrict__ Cparam,
                                                    int N, int K) {
    const int BM = 128, BN = 128, BK = 16;
    __shared__ float As[BK][BM];
    __shared__ float Bs[BK][BN];

    const float* __restrict__ A = (MODE == 0) ? Aparam : g_att;
    const float* __restrict__ Bmat = (MODE == 0) ? g_wq : g_wo;

    int tid = threadIdx.x;
    int tx = tid & 15, ty = tid >> 4;
    int m0 = (int)blockIdx.y * BM;
    int n0 = (int)blockIdx.x * BN;

    float acc[8][8];
#pragma unroll
    for (int i = 0; i < 8; i++)
#pragma unroll
        for (int j = 0; j < 8; j++) acc[i][j] = 0.f;

    for (int k0 = 0; k0 < K; k0 += BK) {
#pragma unroll
        for (int li = 0; li < 2; li++) {
            int idx = tid + li * 256;        // 0..511
            int row = idx >> 2, c4 = idx & 3;
            float4 va = *(const float4*)(A + (size_t)(m0 + row) * K + k0 + c4 * 4);
            As[c4 * 4 + 0][row] = va.x;
            As[c4 * 4 + 1][row] = va.y;
            As[c4 * 4 + 2][row] = va.z;
            As[c4 * 4 + 3][row] = va.w;
            float4 vb = *(const float4*)(Bmat + (size_t)(n0 + row) * K + k0 + c4 * 4);
            Bs[c4 * 4 + 0][row] = vb.x;
            Bs[c4 * 4 + 1][row] = vb.y;
            Bs[c4 * 4 + 2][row] = vb.z;
            Bs[c4 * 4 + 3][row] = vb.w;
        }
        __syncthreads();
#pragma unroll
        for (int kk = 0; kk < BK; kk++) {
            float ra[8], rb[8];
            *(float4*)(ra) = *(const float4*)&As[kk][ty * 8];
            *(float4*)(ra + 4) = *(const float4*)&As[kk][ty * 8 + 4];
            *(float4*)(rb) = *(const float4*)&Bs[kk][tx * 8];
            *(float4*)(rb + 4) = *(const float4*)&Bs[kk][tx * 8 + 4];
#pragma unroll
            for (int i = 0; i < 8; i++)
#pragma unroll
                for (int j = 0; j < 8; j++) acc[i][j] += ra[i] * rb[j];
        }
        __syncthreads();
    }

    if (MODE == 0) {
#pragma unroll
        for (int i = 0; i < 8; i++) {
            int m = m0 + ty * 8 + i;
            int b = m >> 11;          // /T (2048)
            int t = m & 2047;
#pragma unroll
            for (int jj = 0; jj < 2; jj++) {
                int n = n0 + tx * 8 + jj * 4;
                int part = n >> 10;   // 0:q 1:k 2:v
                int c = n & 1023;
                int h = c >> 6;
                int d = c & 63;
                float* dst = (part == 0) ? g_q : (part == 1) ? g_k : g_v;
                float4 val = make_float4(acc[i][jj * 4 + 0], acc[i][jj * 4 + 1],
                                         acc[i][jj * 4 + 2], acc[i][jj * 4 + 3]);
                *(float4*)&dst[((size_t)(b * Hh + h) * Tt + t) * Dd + d] = val;
            }
        }
    } else {
#pragma unroll
        for (int i = 0; i < 8; i++) {
            int m = m0 + ty * 8 + i;
#pragma unroll
            for (int jj = 0; jj < 2; jj++) {
                int n = n0 + tx * 8 + jj * 4;
                float4 val = make_float4(acc[i][jj * 4 + 0], acc[i][jj * 4 + 1],
                                         acc[i][jj * 4 + 2], acc[i][jj * 4 + 3]);
                *(float4*)&Cparam[(size_t)m * N + n] = val;
            }
        }
    }
}

// -------------------- fp32 flash attention, causal --------------------
// grid: (T/64, B*H), block: 256 (16x16 threads, 4x4 per thread)
// dyn smem: Qts[64][64](d-major) | Kts[64][64](d-major) | Vs[64][64] | Pts[64][65]
#define P_STRIDE 65
#define SMEM_ATTN_BYTES ((4096 * 3 + 64 * P_STRIDE) * 4)   // 65792

__global__ __launch_bounds__(256) void flash_attn_kernel() {
    extern __shared__ float smem[];
    float* Qts = smem;
    float* Kts = smem + 4096;
    float* Vs = smem + 8192;
    float* Pts = smem + 12288;

    int bh = blockIdx.y;
    int qt = blockIdx.x;
    int tid = threadIdx.x;
    int tx = tid & 15, ty = tid >> 4;
    int r0 = ty * 4, c0 = tx * 4;

    const float* Qp = g_q + ((size_t)bh * Tt + qt * 64) * Dd;

    // load Q transposed (d-major), pre-scaled by 1/sqrt(D) = 0.125
#pragma unroll
    for (int li = 0; li < 4; li++) {
        int i = tid + li * 256;           // 0..1023
        int row = i >> 4, c4 = i & 15;
        float4 v = *(const float4*)(Qp + row * 64 + c4 * 4);
        Qts[(c4 * 4 + 0) * 64 + row] = v.x * 0.125f;
        Qts[(c4 * 4 + 1) * 64 + row] = v.y * 0.125f;
        Qts[(c4 * 4 + 2) * 64 + row] = v.z * 0.125f;
        Qts[(c4 * 4 + 3) * 64 + row] = v.w * 0.125f;
    }

    float m_i[4] = {-1e30f, -1e30f, -1e30f, -1e30f};
    float l_i[4] = {0.f, 0.f, 0.f, 0.f};
    float O[4][4];
#pragma unroll
    for (int i = 0; i < 4; i++)
#pragma unroll
        for (int j = 0; j < 4; j++) O[i][j] = 0.f;

    for (int kt = 0; kt <= qt; kt++) {
        const float* Kp = g_k + ((size_t)bh * Tt + kt * 64) * Dd;
        const float* Vp = g_v + ((size_t)bh * Tt + kt * 64) * Dd;
        __syncthreads();   // previous PV done before overwriting K/V tiles
#pragma unroll
        for (int li = 0; li < 4; li++) {
            int i = tid + li * 256;
            int row = i >> 4, c4 = i & 15;
            float4 kv = *(const float4*)(Kp + row * 64 + c4 * 4);
            Kts[(c4 * 4 + 0) * 64 + row] = kv.x;
            Kts[(c4 * 4 + 1) * 64 + row] = kv.y;
            Kts[(c4 * 4 + 2) * 64 + row] = kv.z;
            Kts[(c4 * 4 + 3) * 64 + row] = kv.w;
            float4 vv = *(const float4*)(Vp + row * 64 + c4 * 4);
            *(float4*)&Vs[row * 64 + c4 * 4] = vv;
        }
        __syncthreads();

        // S = (Q * 1/8) K^T  -> 4x4 per thread
        float s[4][4];
#pragma unroll
        for (int i = 0; i < 4; i++)
#pragma unroll
            for (int j = 0; j < 4; j++) s[i][j] = 0.f;
#pragma unroll 8
        for (int d = 0; d < 64; d++) {
            float4 qa = *(const float4*)&Qts[d * 64 + r0];
            float4 kb = *(const float4*)&Kts[d * 64 + c0];
            float qv[4] = {qa.x, qa.y, qa.z, qa.w};
            float kv[4] = {kb.x, kb.y, kb.z, kb.w};
#pragma unroll
            for (int i = 0; i < 4; i++)
#pragma unroll
                for (int j = 0; j < 4; j++) s[i][j] += qv[i] * kv[j];
        }

        if (kt == qt) {
#pragma unroll
            for (int i = 0; i < 4; i++)
#pragma unroll
                for (int j = 0; j < 4; j++)
                    if (c0 + j > r0 + i) s[i][j] = -1e30f;
        }

        // online softmax per row (row group = 16 lanes sharing ty)
#pragma unroll
        for (int i = 0; i < 4; i++) {
            float rm = fmaxf(fmaxf(s[i][0], s[i][1]), fmaxf(s[i][2], s[i][3]));
            rm = fmaxf(rm, __shfl_xor_sync(0xffffffffu, rm, 1));
            rm = fmaxf(rm, __shfl_xor_sync(0xffffffffu, rm, 2));
            rm = fmaxf(rm, __shfl_xor_sync(0xffffffffu, rm, 4));
            rm = fmaxf(rm, __shfl_xor_sync(0xffffffffu, rm, 8));
            float mnew = fmaxf(m_i[i], rm);
            float alpha = __expf(m_i[i] - mnew);
            float rs = 0.f;
#pragma unroll
            for (int j = 0; j < 4; j++) {
                s[i][j] = __expf(s[i][j] - mnew);
                rs += s[i][j];
            }
            rs += __shfl_xor_sync(0xffffffffu, rs, 1);
            rs += __shfl_xor_sync(0xffffffffu, rs, 2);
            rs += __shfl_xor_sync(0xffffffffu, rs, 4);
            rs += __shfl_xor_sync(0xffffffffu, rs, 8);
            l_i[i] = l_i[i] * alpha + rs;
            m_i[i] = mnew;
#pragma unroll
            for (int j = 0; j < 4; j++) O[i][j] *= alpha;
            // stage P (key-major, padded stride -> ~2-way conflicts)
#pragma unroll
            for (int j = 0; j < 4; j++) Pts[(c0 + j) * P_STRIDE + (r0 + i)] = s[i][j];
        }
        __syncwarp();   // P rows a thread reads are written by its own half-warp

        // O += P @ V
#pragma unroll 4
        for (int kk = 0; kk < 64; kk++) {
            float4 vb = *(const float4*)&Vs[kk * 64 + c0];
            float vv[4] = {vb.x, vb.y, vb.z, vb.w};
#pragma unroll
            for (int i = 0; i < 4; i++) {
                float pa = Pts[kk * P_STRIDE + r0 + i];
#pragma unroll
                for (int j = 0; j < 4; j++) O[i][j] += pa * vv[j];
            }
        }
    }

    // epilogue: normalize and write [B,T,H*D] row-major
    int b = bh >> 4, h = bh & 15;
#pragma unroll
    for (int i = 0; i < 4; i++) {
        int t = qt * 64 + r0 + i;
        float inv = 1.0f / l_i[i];
        float4 o = make_float4(O[i][0] * inv, O[i][1] * inv, O[i][2] * inv, O[i][3] * inv);
        *(float4*)&g_att[(size_t)(b * Tt + t) * Cc + h * 64 + c0] = o;
    }
}

// -------------------- launch --------------------
extern "C" void kernel_launch(void* const* d_in, const int* in_sizes, int n_in,
                              void* d_out, int out_size) {
    (void)in_sizes; (void)n_in; (void)out_size;
    const float* x = (const float*)d_in[0];
    const float* w_qkv = (const float*)d_in[1];
    const float* w_out = (const float*)d_in[2];
    float* out = (float*)d_out;

    // quantize w_qkv
    abssum_partial_kernel<<<1024, 256>>>(w_qkv, NW_QKV);
    finalize_scale_kernel<<<1, 256>>>(1.0f / (float)NW_QKV);
    quantize_kernel<0><<<NW_QKV / 4 / 256, 256>>>(w_qkv, NW_QKV / 4);
    // quantize w_out
    abssum_partial_kernel<<<1024, 256>>>(w_out, NW_OUT);
    finalize_scale_kernel<<<1, 256>>>(1.0f / (float)NW_OUT);
    quantize_kernel<1><<<NW_OUT / 4 / 256, 256>>>(w_out, NW_OUT / 4);

    // qkv projection (scatter into per-head q/k/v)
    {
        dim3 grid(N_QKV / 128, Mm / 128);
        sgemm_kernel<0><<<grid, 256>>>(x, nullptr, N_QKV, Cc);
    }

    // causal flash attention
    {
        cudaFuncSetAttribute(flash_attn_kernel,
                             cudaFuncAttributeMaxDynamicSharedMemorySize,
                             SMEM_ATTN_BYTES);
        dim3 grid(Tt / 64, Bb * Hh);
        flash_attn_kernel<<<grid, 256, SMEM_ATTN_BYTES>>>();
    }

    // output projection
    {
        dim3 grid(Cc / 128, Mm / 128);
        sgemm_kernel<1><<<grid, 256>>>(nullptr, out, Cc, Cc);
    }
}

// round 5
// speedup vs baseline: 1.4356x; 1.4356x over previous
#include <cuda_runtime.h>
#include <cstdint>

// Problem constants (constexpr, not macros — avoids identifier capture)
constexpr int cB = 4;
constexpr int cT = 2048;
constexpr int cC = 1024;
constexpr int cH = 16;
constexpr int cD = 64;
constexpr int cM = cB * cT;          // 8192 rows
constexpr int cNqkv = 3 * cC;        // 3072
constexpr int cNWq = cNqkv * cC;     // 3,145,728
constexpr int cNWo = cC * cC;        // 1,048,576
constexpr int cK = 1024;

// -------------------- device scratch (no allocations allowed) --------------------
__device__ float g_partial[1024];
__device__ float g_scale_inv;                  // 1/scale for current weight tensor
__device__ float g_wq[cNWq];                   // ternary qkv weights (fp32 {-1,0,1})
__device__ float g_wo[cNWo];                   // ternary out-proj weights
__device__ float g_q[cB * cH * cT * cD];       // [B,H,T,D]
__device__ float g_k[cB * cH * cT * cD];
__device__ float g_v[cB * cH * cT * cD];
__device__ float g_att[cM * cC];               // attention output, [B,T,C] row-major

// -------------------- absmean scale: deterministic 2-pass reduction --------------------
__global__ void abssum_partial_kernel(const float* __restrict__ w, int n) {
    __shared__ float sd[256];
    int chunk = (n + (int)gridDim.x - 1) / (int)gridDim.x;
    int start = (int)blockIdx.x * chunk;
    int end = start + chunk; if (end > n) end = n;
    float s = 0.f;
    for (int i = start + (int)threadIdx.x; i < end; i += 256) s += fabsf(w[i]);
    sd[threadIdx.x] = s;
    __syncthreads();
    for (int o = 128; o > 0; o >>= 1) {
        if ((int)threadIdx.x < o) sd[threadIdx.x] += sd[threadIdx.x + o];
        __syncthreads();
    }
    if (threadIdx.x == 0) g_partial[blockIdx.x] = sd[0];
}

__global__ void finalize_scale_kernel(float inv_n) {
    __shared__ float sd[256];
    float s = 0.f;
    for (int i = threadIdx.x; i < 1024; i += 256) s += g_partial[i];
    sd[threadIdx.x] = s;
    __syncthreads();
    for (int o = 128; o > 0; o >>= 1) {
        if ((int)threadIdx.x < o) sd[threadIdx.x] += sd[threadIdx.x + o];
        __syncthreads();
    }
    if (threadIdx.x == 0) {
        float sc = fmaxf(sd[0] * inv_n, 1e-8f);
        g_scale_inv = 1.0f / sc;
    }
}

// WHICH: 0 -> g_wq, 1 -> g_wo.  n4 = element count / 4
template <int WHICH>
__global__ void quantize_kernel(const float* __restrict__ w, int n4) {
    int i = (int)blockIdx.x * 256 + (int)threadIdx.x;
    if (i >= n4) return;
    float inv = g_scale_inv;
    float4 v = ((const float4*)w)[i];
    float4 r;
    r.x = fminf(1.f, fmaxf(-1.f, rintf(v.x * inv)));
    r.y = fminf(1.f, fmaxf(-1.f, rintf(v.y * inv)));
    r.z = fminf(1.f, fmaxf(-1.f, rintf(v.z * inv)));
    r.w = fminf(1.f, fmaxf(-1.f, rintf(v.w * inv)));
    float4* dst = (WHICH == 0) ? (float4*)g_wq : (float4*)g_wo;
    dst[i] = r;
}

// -------------------- 2xTF32 tensor-core GEMM (B side exact ternary) --------------------
// C[m][n] = sum_k A[m][k] * B[n][k], K = 1024 (both GEMMs)
// A split: a = hi + lo, hi = tf32(a), lo = tf32(a - hi)  -> ~fp32 precision
// MODE 0: A = x (param), B = g_wq, scatter-epilogue into g_q/g_k/g_v ([B,H,T,D])
// MODE 1: A = g_att,     B = g_wo, C = out (param), plain row-major
// CTA tile 128x128x32, 8 warps as 4(m) x 2(n), warp tile 32x64, mma m16n8k8.

constexpr int GBM = 128;
constexpr int GBK = 32;
constexpr int SROW = 36;                 // padded row stride (floats); 144B, 16B-aligned
constexpr int SBUF = GBM * SROW;         // floats per buffer per matrix
constexpr int GEMM_SMEM_BYTES = 2 * 2 * SBUF * 4;   // 73728 B

__device__ __forceinline__ void cp_async16(uint32_t smem_addr, const void* gptr) {
    asm volatile("cp.async.cg.shared.global [%0], [%1], 16;\n" ::"r"(smem_addr), "l"(gptr));
}
__device__ __forceinline__ void cp_commit() { asm volatile("cp.async.commit_group;\n"); }
template <int N>
__device__ __forceinline__ void cp_wait() { asm volatile("cp.async.wait_group %0;\n" ::"n"(N)); }

__device__ __forceinline__ uint32_t f2tf32(float f) {
    uint32_t u;
    asm("cvt.rna.tf32.f32 %0, %1;\n" : "=r"(u) : "f"(f));
    return u;
}

__device__ __forceinline__ void mma_tf32(float* d, const uint32_t* a, const uint32_t* b) {
    asm volatile(
        "mma.sync.aligned.m16n8k8.row.col.f32.tf32.tf32.f32 "
        "{%0,%1,%2,%3}, {%4,%5,%6,%7}, {%8,%9}, {%0,%1,%2,%3};\n"
        : "+f"(d[0]), "+f"(d[1]), "+f"(d[2]), "+f"(d[3])
        : "r"(a[0]), "r"(a[1]), "r"(a[2]), "r"(a[3]), "r"(b[0]), "r"(b[1]));
}

template <int MODE>
__global__ __launch_bounds__(256) void gemm_tf32_kernel(const float* __restrict__ Aparam,
                                                        float* __restrict__ Cparam) {
    extern __shared__ float smem[];
    float* As = smem;                 // [2][128][SROW]
    float* Bs = smem + 2 * SBUF;      // [2][128][SROW]

    const float* __restrict__ A = (MODE == 0) ? Aparam : g_att;
    const float* __restrict__ Wmat = (MODE == 0) ? g_wq : g_wo;

    const int tid = threadIdx.x;
    const int lane = tid & 31, wid = tid >> 5;
    const int warp_m = (wid >> 1) * 32;     // 0,32,64,96
    const int warp_n = (wid & 1) * 64;      // 0,64
    const int g = lane >> 2, l4 = lane & 3;

    const int m0 = (int)blockIdx.y * GBM;
    const int n0 = (int)blockIdx.x * GBM;

    float acc[2][8][4];
#pragma unroll
    for (int mt = 0; mt < 2; mt++)
#pragma unroll
        for (int nt = 0; nt < 8; nt++)
#pragma unroll
            for (int c = 0; c < 4; c++) acc[mt][nt][c] = 0.f;

    uint32_t sA = (uint32_t)__cvta_generic_to_shared(As);
    uint32_t sB = (uint32_t)__cvta_generic_to_shared(Bs);

    // 1024 16B-chunks per matrix per stage (128 rows x 8 chunks)
    auto load_stage = [&](int s) {
        int buf = s & 1;
        int k0 = s * GBK;
#pragma unroll
        for (int i = 0; i < 4; i++) {
            int chunk = tid + i * 256;            // 0..1023
            int row = chunk >> 3, c8 = chunk & 7;
            uint32_t off = (uint32_t)((buf * SBUF + row * SROW + c8 * 4) * 4);
            cp_async16(sA + off, A + (size_t)(m0 + row) * cK + k0 + c8 * 4);
            cp_async16(sB + off, Wmat + (size_t)(n0 + row) * cK + k0 + c8 * 4);
        }
        cp_commit();
    };

    const int NS = cK / GBK;   // 32
    load_stage(0);

    for (int s = 0; s < NS; s++) {
        if (s + 1 < NS) {
            load_stage(s + 1);
            cp_wait<1>();
        } else {
            cp_wait<0>();
        }
        __syncthreads();

        const float* Abuf = As + (s & 1) * SBUF;
        const float* Bbuf = Bs + (s & 1) * SBUF;
#pragma unroll
        for (int kk = 0; kk < 4; kk++) {
            const int k = kk * 8;
            uint32_t ah[2][4], al[2][4], bf[8][2];
#pragma unroll
            for (int mt = 0; mt < 2; mt++) {
                const float* p = Abuf + (warp_m + mt * 16 + g) * SROW + k + l4;
                float a0 = p[0], a1 = p[8 * SROW], a2 = p[4], a3 = p[8 * SROW + 4];
                ah[mt][0] = f2tf32(a0);
                ah[mt][1] = f2tf32(a1);
                ah[mt][2] = f2tf32(a2);
                ah[mt][3] = f2tf32(a3);
                al[mt][0] = f2tf32(a0 - __uint_as_float(ah[mt][0]));
                al[mt][1] = f2tf32(a1 - __uint_as_float(ah[mt][1]));
                al[mt][2] = f2tf32(a2 - __uint_as_float(ah[mt][2]));
                al[mt][3] = f2tf32(a3 - __uint_as_float(ah[mt][3]));
            }
#pragma unroll
            for (int nt = 0; nt < 8; nt++) {
                const float* p = Bbuf + (warp_n + nt * 8 + g) * SROW + k + l4;
                bf[nt][0] = f2tf32(p[0]);   // ternary -> exact in tf32
                bf[nt][1] = f2tf32(p[4]);
            }
#pragma unroll
            for (int mt = 0; mt < 2; mt++)
#pragma unroll
                for (int nt = 0; nt < 8; nt++) {
                    mma_tf32(acc[mt][nt], al[mt], bf[nt]);   // low part first
                    mma_tf32(acc[mt][nt], ah[mt], bf[nt]);   // high part
                }
        }
        __syncthreads();
    }

    // epilogue: rows (g, g+8) per 16-row m-tile; cols l4*2,+1 per 8-col n-tile
#pragma unroll
    for (int mt = 0; mt < 2; mt++) {
#pragma unroll
        for (int h8 = 0; h8 < 2; h8++) {
            int m = m0 + warp_m + mt * 16 + g + h8 * 8;
#pragma unroll
            for (int nt = 0; nt < 8; nt++) {
                int n = n0 + warp_n + nt * 8 + l4 * 2;
                float2 val = make_float2(acc[mt][nt][h8 * 2 + 0], acc[mt][nt][h8 * 2 + 1]);
                if (MODE == 0) {
                    int b = m >> 11;          // / T
                    int t = m & 2047;
                    int part = n >> 10;       // 0:q 1:k 2:v
                    int c = n & 1023;
                    int hh = c >> 6;
                    int d = c & 63;
                    float* dst = (part == 0) ? g_q : (part == 1) ? g_k : g_v;
                    *(float2*)&dst[((size_t)(b * cH + hh) * cT + t) * cD + d] = val;
                } else {
                    *(float2*)&Cparam[(size_t)m * cC + n] = val;
                }
            }
        }
    }
}

// -------------------- fp32 flash attention, causal --------------------
// grid: (T/64, B*H), block: 256 (16x16 threads, 4x4 per thread)
constexpr int P_STRIDE = 65;
constexpr int SMEM_ATTN_BYTES = (4096 * 3 + 64 * P_STRIDE) * 4;   // 65792

__global__ __launch_bounds__(256) void flash_attn_kernel() {
    extern __shared__ float smem[];
    float* Qts = smem;
    float* Kts = smem + 4096;
    float* Vs = smem + 8192;
    float* Pts = smem + 12288;

    int bh = blockIdx.y;
    int qt = blockIdx.x;
    int tid = threadIdx.x;
    int tx = tid & 15, ty = tid >> 4;
    int r0 = ty * 4, c0 = tx * 4;

    const float* Qp = g_q + ((size_t)bh * cT + qt * 64) * cD;

#pragma unroll
    for (int li = 0; li < 4; li++) {
        int i = tid + li * 256;
        int row = i >> 4, c4 = i & 15;
        float4 v = *(const float4*)(Qp + row * 64 + c4 * 4);
        Qts[(c4 * 4 + 0) * 64 + row] = v.x * 0.125f;
        Qts[(c4 * 4 + 1) * 64 + row] = v.y * 0.125f;
        Qts[(c4 * 4 + 2) * 64 + row] = v.z * 0.125f;
        Qts[(c4 * 4 + 3) * 64 + row] = v.w * 0.125f;
    }

    float m_i[4] = {-1e30f, -1e30f, -1e30f, -1e30f};
    float l_i[4] = {0.f, 0.f, 0.f, 0.f};
    float O[4][4];
#pragma unroll
    for (int i = 0; i < 4; i++)
#pragma unroll
        for (int j = 0; j < 4; j++) O[i][j] = 0.f;

    for (int kt = 0; kt <= qt; kt++) {
        const float* Kp = g_k + ((size_t)bh * cT + kt * 64) * cD;
        const float* Vp = g_v + ((size_t)bh * cT + kt * 64) * cD;
        __syncthreads();
#pragma unroll
        for (int li = 0; li < 4; li++) {
            int i = tid + li * 256;
            int row = i >> 4, c4 = i & 15;
            float4 kv = *(const float4*)(Kp + row * 64 + c4 * 4);
            Kts[(c4 * 4 + 0) * 64 + row] = kv.x;
            Kts[(c4 * 4 + 1) * 64 + row] = kv.y;
            Kts[(c4 * 4 + 2) * 64 + row] = kv.z;
            Kts[(c4 * 4 + 3) * 64 + row] = kv.w;
            float4 vv = *(const float4*)(Vp + row * 64 + c4 * 4);
            *(float4*)&Vs[row * 64 + c4 * 4] = vv;
        }
        __syncthreads();

        float s[4][4];
#pragma unroll
        for (int i = 0; i < 4; i++)
#pragma unroll
            for (int j = 0; j < 4; j++) s[i][j] = 0.f;
#pragma unroll 8
        for (int d = 0; d < 64; d++) {
            float4 qa = *(const float4*)&Qts[d * 64 + r0];
            float4 kb = *(const float4*)&Kts[d * 64 + c0];
            float qv[4] = {qa.x, qa.y, qa.z, qa.w};
            float kv[4] = {kb.x, kb.y, kb.z, kb.w};
#pragma unroll
            for (int i = 0; i < 4; i++)
#pragma unroll
                for (int j = 0; j < 4; j++) s[i][j] += qv[i] * kv[j];
        }

        if (kt == qt) {
#pragma unroll
            for (int i = 0; i < 4; i++)
#pragma unroll
                for (int j = 0; j < 4; j++)
                    if (c0 + j > r0 + i) s[i][j] = -1e30f;
        }

#pragma unroll
        for (int i = 0; i < 4; i++) {
            float rm = fmaxf(fmaxf(s[i][0], s[i][1]), fmaxf(s[i][2], s[i][3]));
            rm = fmaxf(rm, __shfl_xor_sync(0xffffffffu, rm, 1));
            rm = fmaxf(rm, __shfl_xor_sync(0xffffffffu, rm, 2));
            rm = fmaxf(rm, __shfl_xor_sync(0xffffffffu, rm, 4));
            rm = fmaxf(rm, __shfl_xor_sync(0xffffffffu, rm, 8));
            float mnew = fmaxf(m_i[i], rm);
            float alpha = __expf(m_i[i] - mnew);
            float rs = 0.f;
#pragma unroll
            for (int j = 0; j < 4; j++) {
                s[i][j] = __expf(s[i][j] - mnew);
                rs += s[i][j];
            }
            rs += __shfl_xor_sync(0xffffffffu, rs, 1);
            rs += __shfl_xor_sync(0xffffffffu, rs, 2);
            rs += __shfl_xor_sync(0xffffffffu, rs, 4);
            rs += __shfl_xor_sync(0xffffffffu, rs, 8);
            l_i[i] = l_i[i] * alpha + rs;
            m_i[i] = mnew;
#pragma unroll
            for (int j = 0; j < 4; j++) O[i][j] *= alpha;
#pragma unroll
            for (int j = 0; j < 4; j++) Pts[(c0 + j) * P_STRIDE + (r0 + i)] = s[i][j];
        }
        __syncwarp();

#pragma unroll 4
        for (int kk = 0; kk < 64; kk++) {
            float4 vb = *(const float4*)&Vs[kk * 64 + c0];
            float vv[4] = {vb.x, vb.y, vb.z, vb.w};
#pragma unroll
            for (int i = 0; i < 4; i++) {
                float pa = Pts[kk * P_STRIDE + r0 + i];
#pragma unroll
                for (int j = 0; j < 4; j++) O[i][j] += pa * vv[j];
            }
        }
    }

    int b = bh >> 4, h = bh & 15;
#pragma unroll
    for (int i = 0; i < 4; i++) {
        int t = qt * 64 + r0 + i;
        float inv = 1.0f / l_i[i];
        float4 o = make_float4(O[i][0] * inv, O[i][1] * inv, O[i][2] * inv, O[i][3] * inv);
        *(float4*)&g_att[(size_t)(b * cT + t) * cC + h * 64 + c0] = o;
    }
}

// -------------------- launch --------------------
extern "C" void kernel_launch(void* const* d_in, const int* in_sizes, int n_in,
                              void* d_out, int out_size) {
    (void)in_sizes; (void)n_in; (void)out_size;
    const float* x = (const float*)d_in[0];
    const float* w_qkv = (const float*)d_in[1];
    const float* w_out = (const float*)d_in[2];
    float* out = (float*)d_out;

    // quantize w_qkv
    abssum_partial_kernel<<<1024, 256>>>(w_qkv, cNWq);
    finalize_scale_kernel<<<1, 256>>>(1.0f / (float)cNWq);
    quantize_kernel<0><<<cNWq / 4 / 256, 256>>>(w_qkv, cNWq / 4);
    // quantize w_out
    abssum_partial_kernel<<<1024, 256>>>(w_out, cNWo);
    finalize_scale_kernel<<<1, 256>>>(1.0f / (float)cNWo);
    quantize_kernel<1><<<cNWo / 4 / 256, 256>>>(w_out, cNWo / 4);

    // qkv projection: 2xtf32 tensor cores, scatter into per-head q/k/v
    {
        cudaFuncSetAttribute(gemm_tf32_kernel<0>,
                             cudaFuncAttributeMaxDynamicSharedMemorySize, GEMM_SMEM_BYTES);
        dim3 grid(cNqkv / 128, cM / 128);
        gemm_tf32_kernel<0><<<grid, 256, GEMM_SMEM_BYTES>>>(x, nullptr);
    }

    // causal flash attention
    {
        cudaFuncSetAttribute(flash_attn_kernel,
                             cudaFuncAttributeMaxDynamicSharedMemorySize, SMEM_ATTN_BYTES);
        dim3 grid(cT / 64, cB * cH);
        flash_attn_kernel<<<grid, 256, SMEM_ATTN_BYTES>>>();
    }

    // output projection: 2xtf32 tensor cores
    {
        cudaFuncSetAttribute(gemm_tf32_kernel<1>,
                             cudaFuncAttributeMaxDynamicSharedMemorySize, GEMM_SMEM_BYTES);
        dim3 grid(cC / 128, cM / 128);
        gemm_tf32_kernel<1><<<grid, 256, GEMM_SMEM_BYTES>>>(nullptr, out);
    }
}

// round 6
// speedup vs baseline: 1.8566x; 1.2933x over previous
#include <cuda_runtime.h>
#include <cstdint>

// Problem constants (constexpr, not macros — avoids identifier capture)
constexpr int cB = 4;
constexpr int cT = 2048;
constexpr int cC = 1024;
constexpr int cH = 16;
constexpr int cD = 64;
constexpr int cM = cB * cT;          // 8192 rows
constexpr int cNqkv = 3 * cC;        // 3072
constexpr int cNWq = cNqkv * cC;     // 3,145,728
constexpr int cNWo = cC * cC;        // 1,048,576
constexpr int cK = 1024;

// -------------------- device scratch (no allocations allowed) --------------------
__device__ float g_partial[1024];
__device__ float g_scale_inv;
__device__ float g_wq[cNWq];                   // ternary qkv weights (fp32 {-1,0,1})
__device__ float g_wo[cNWo];                   // ternary out-proj weights
__device__ float g_q[cB * cH * cT * cD];       // [B,H,T,D]
__device__ float g_k[cB * cH * cT * cD];
__device__ float g_v[cB * cH * cT * cD];
__device__ float g_vt[cB * cH * cD * cT];      // V transposed: [B,H,D,T]
__device__ float g_att[cM * cC];               // attention output, [B,T,C] row-major

// -------------------- absmean scale: deterministic 2-pass reduction --------------------
__global__ void abssum_partial_kernel(const float* __restrict__ w, int n) {
    __shared__ float sd[256];
    int chunk = (n + (int)gridDim.x - 1) / (int)gridDim.x;
    int start = (int)blockIdx.x * chunk;
    int end = start + chunk; if (end > n) end = n;
    float s = 0.f;
    for (int i = start + (int)threadIdx.x; i < end; i += 256) s += fabsf(w[i]);
    sd[threadIdx.x] = s;
    __syncthreads();
    for (int o = 128; o > 0; o >>= 1) {
        if ((int)threadIdx.x < o) sd[threadIdx.x] += sd[threadIdx.x + o];
        __syncthreads();
    }
    if (threadIdx.x == 0) g_partial[blockIdx.x] = sd[0];
}

__global__ void finalize_scale_kernel(float inv_n) {
    __shared__ float sd[256];
    float s = 0.f;
    for (int i = threadIdx.x; i < 1024; i += 256) s += g_partial[i];
    sd[threadIdx.x] = s;
    __syncthreads();
    for (int o = 128; o > 0; o >>= 1) {
        if ((int)threadIdx.x < o) sd[threadIdx.x] += sd[threadIdx.x + o];
        __syncthreads();
    }
    if (threadIdx.x == 0) {
        float sc = fmaxf(sd[0] * inv_n, 1e-8f);
        g_scale_inv = 1.0f / sc;
    }
}

template <int WHICH>
__global__ void quantize_kernel(const float* __restrict__ w, int n4) {
    int i = (int)blockIdx.x * 256 + (int)threadIdx.x;
    if (i >= n4) return;
    float inv = g_scale_inv;
    float4 v = ((const float4*)w)[i];
    float4 r;
    r.x = fminf(1.f, fmaxf(-1.f, rintf(v.x * inv)));
    r.y = fminf(1.f, fmaxf(-1.f, rintf(v.y * inv)));
    r.z = fminf(1.f, fmaxf(-1.f, rintf(v.z * inv)));
    r.w = fminf(1.f, fmaxf(-1.f, rintf(v.w * inv)));
    float4* dst = (WHICH == 0) ? (float4*)g_wq : (float4*)g_wo;
    dst[i] = r;
}

// -------------------- tf32 helpers --------------------
__device__ __forceinline__ void cp_async16(uint32_t smem_addr, const void* gptr) {
    asm volatile("cp.async.cg.shared.global [%0], [%1], 16;\n" ::"r"(smem_addr), "l"(gptr));
}
__device__ __forceinline__ void cp_commit() { asm volatile("cp.async.commit_group;\n"); }
template <int N>
__device__ __forceinline__ void cp_wait() { asm volatile("cp.async.wait_group %0;\n" ::"n"(N)); }

__device__ __forceinline__ uint32_t f2tf32(float f) {
    uint32_t u;
    asm("cvt.rna.tf32.f32 %0, %1;\n" : "=r"(u) : "f"(f));
    return u;
}
__device__ __forceinline__ void split_tf32(float v, uint32_t& hi, uint32_t& lo) {
    hi = f2tf32(v);
    lo = f2tf32(v - __uint_as_float(hi));
}
__device__ __forceinline__ void mma_tf32(float* d, const uint32_t* a, const uint32_t* b) {
    asm volatile(
        "mma.sync.aligned.m16n8k8.row.col.f32.tf32.tf32.f32 "
        "{%0,%1,%2,%3}, {%4,%5,%6,%7}, {%8,%9}, {%0,%1,%2,%3};\n"
        : "+f"(d[0]), "+f"(d[1]), "+f"(d[2]), "+f"(d[3])
        : "r"(a[0]), "r"(a[1]), "r"(a[2]), "r"(a[3]), "r"(b[0]), "r"(b[1]));
}
__device__ __forceinline__ void ldsm4(uint32_t addr, uint32_t* r) {
    asm volatile("ldmatrix.sync.aligned.m8n8.x4.shared.b16 {%0,%1,%2,%3}, [%4];\n"
                 : "=r"(r[0]), "=r"(r[1]), "=r"(r[2]), "=r"(r[3]) : "r"(addr));
}

// -------------------- 2xTF32 tensor-core GEMM (B side exact ternary) --------------------
constexpr int GBM = 128;
constexpr int GBK = 32;
constexpr int SROW = 36;
constexpr int SBUF = GBM * SROW;
constexpr int GEMM_SMEM_BYTES = 2 * 2 * SBUF * 4;   // 73728 B

template <int MODE>
__global__ __launch_bounds__(256) void gemm_tf32_kernel(const float* __restrict__ Aparam,
                                                        float* __restrict__ Cparam) {
    extern __shared__ float smem[];
    float* As = smem;
    float* Bs = smem + 2 * SBUF;

    const float* __restrict__ A = (MODE == 0) ? Aparam : g_att;
    const float* __restrict__ Wmat = (MODE == 0) ? g_wq : g_wo;

    const int tid = threadIdx.x;
    const int lane = tid & 31, wid = tid >> 5;
    const int warp_m = (wid >> 1) * 32;
    const int warp_n = (wid & 1) * 64;
    const int g = lane >> 2, l4 = lane & 3;

    const int m0 = (int)blockIdx.y * GBM;
    const int n0 = (int)blockIdx.x * GBM;

    float acc[2][8][4];
#pragma unroll
    for (int mt = 0; mt < 2; mt++)
#pragma unroll
        for (int nt = 0; nt < 8; nt++)
#pragma unroll
            for (int c = 0; c < 4; c++) acc[mt][nt][c] = 0.f;

    uint32_t sA = (uint32_t)__cvta_generic_to_shared(As);
    uint32_t sB = (uint32_t)__cvta_generic_to_shared(Bs);

    auto load_stage = [&](int s) {
        int buf = s & 1;
        int k0 = s * GBK;
#pragma unroll
        for (int i = 0; i < 4; i++) {
            int chunk = tid + i * 256;
            int row = chunk >> 3, c8 = chunk & 7;
            uint32_t off = (uint32_t)((buf * SBUF + row * SROW + c8 * 4) * 4);
            cp_async16(sA + off, A + (size_t)(m0 + row) * cK + k0 + c8 * 4);
            cp_async16(sB + off, Wmat + (size_t)(n0 + row) * cK + k0 + c8 * 4);
        }
        cp_commit();
    };

    const int NS = cK / GBK;
    load_stage(0);

    for (int s = 0; s < NS; s++) {
        if (s + 1 < NS) {
            load_stage(s + 1);
            cp_wait<1>();
        } else {
            cp_wait<0>();
        }
        __syncthreads();

        const float* Abuf = As + (s & 1) * SBUF;
        const uint32_t* Bu = (const uint32_t*)(Bs + (s & 1) * SBUF);
#pragma unroll
        for (int kk = 0; kk < 4; kk++) {
            const int k = kk * 8;
            uint32_t ah[2][4], al[2][4], bf[8][2];
#pragma unroll
            for (int mt = 0; mt < 2; mt++) {
                const float* p = Abuf + (warp_m + mt * 16 + g) * SROW + k + l4;
                float a0 = p[0], a1 = p[8 * SROW], a2 = p[4], a3 = p[8 * SROW + 4];
                split_tf32(a0, ah[mt][0], al[mt][0]);
                split_tf32(a1, ah[mt][1], al[mt][1]);
                split_tf32(a2, ah[mt][2], al[mt][2]);
                split_tf32(a3, ah[mt][3], al[mt][3]);
            }
#pragma unroll
            for (int nt = 0; nt < 8; nt++) {
                const uint32_t* p = Bu + (warp_n + nt * 8 + g) * SROW + k + l4;
                bf[nt][0] = p[0];   // ternary fp32 bits are valid tf32 — no cvt
                bf[nt][1] = p[4];
            }
#pragma unroll
            for (int mt = 0; mt < 2; mt++)
#pragma unroll
                for (int nt = 0; nt < 8; nt++) {
                    mma_tf32(acc[mt][nt], al[mt], bf[nt]);
                    mma_tf32(acc[mt][nt], ah[mt], bf[nt]);
                }
        }
        __syncthreads();
    }

#pragma unroll
    for (int mt = 0; mt < 2; mt++) {
#pragma unroll
        for (int h8 = 0; h8 < 2; h8++) {
            int m = m0 + warp_m + mt * 16 + g + h8 * 8;
#pragma unroll
            for (int nt = 0; nt < 8; nt++) {
                int n = n0 + warp_n + nt * 8 + l4 * 2;
                float2 val = make_float2(acc[mt][nt][h8 * 2 + 0], acc[mt][nt][h8 * 2 + 1]);
                if (MODE == 0) {
                    int b = m >> 11;
                    int t = m & 2047;
                    int part = n >> 10;
                    int c = n & 1023;
                    int hh = c >> 6;
                    int d = c & 63;
                    float* dst = (part == 0) ? g_q : (part == 1) ? g_k : g_v;
                    *(float2*)&dst[((size_t)(b * cH + hh) * cT + t) * cD + d] = val;
                } else {
                    *(float2*)&Cparam[(size_t)m * cC + n] = val;
                }
            }
        }
    }
}

// -------------------- V transpose: g_v [bh][T][D] -> g_vt [bh][D][T] --------------------
__global__ void transpose_v_kernel() {
    __shared__ float tile[32][33];
    int bh = blockIdx.z;
    int t0 = blockIdx.x * 32, d0 = blockIdx.y * 32;
    int tx = threadIdx.x, ty = threadIdx.y;   // 32x8
#pragma unroll
    for (int i = 0; i < 32; i += 8)
        tile[ty + i][tx] = g_v[((size_t)bh * cT + t0 + ty + i) * cD + d0 + tx];
    __syncthreads();
#pragma unroll
    for (int i = 0; i < 32; i += 8)
        g_vt[((size_t)bh * cD + d0 + ty + i) * cT + t0 + tx] = tile[tx][ty + i];
}

// -------------------- tensor-core flash attention (2xtf32, causal) --------------------
// CTA: 128 q-rows, 8 warps x 16 rows; K-tile 64. All operands as tf32 hi/lo smem planes.
constexpr int AST = 68;                    // row stride in u32 (272B, 16B-aligned)
constexpr int QPL = 128 * AST;             // q-sized plane (u32)
constexpr int KPL = 64 * AST;              // k-sized plane
constexpr int ATTN_TC_SMEM = (2 * QPL + 4 * KPL + 2 * QPL) * 4;   // 208896 B

__global__ __launch_bounds__(256) void flash_attn_tc_kernel() {
    extern __shared__ uint32_t smu[];
    uint32_t* QH = smu;
    uint32_t* QL = QH + QPL;
    uint32_t* KH = QL + QPL;
    uint32_t* KL = KH + KPL;
    uint32_t* VH = KL + KPL;
    uint32_t* VL = VH + KPL;
    uint32_t* PH = VL + KPL;
    uint32_t* PL = PH + QPL;

    const int tid = threadIdx.x;
    const int lane = tid & 31, wid = tid >> 5;
    const int g = lane >> 2, l4 = lane & 3;
    const int bh = blockIdx.y;
    const int qt = (int)gridDim.x - 1 - (int)blockIdx.x;   // big tiles first
    const int m0 = wid * 16;

    const uint32_t sbase = (uint32_t)__cvta_generic_to_shared(smu);
    const uint32_t qhB = sbase, qlB = sbase + QPL * 4;
    const uint32_t khB = qlB + QPL * 4, klB = khB + KPL * 4;
    const uint32_t vhB = klB + KPL * 4, vlB = vhB + KPL * 4;
    const uint32_t phB = vlB + KPL * 4, plB = phB + QPL * 4;

    // ldmatrix lane address components
    const int aRow = (lane & 7) + ((lane >> 3) & 1) * 8;   // A-frag pattern
    const int aCol = (lane >> 4) * 4;
    const int bRow = lane & 7;                             // B-frag pattern
    const int bCol = ((lane >> 3) & 3) * 4;

    // ---- load + split Q (pre-scaled by 1/8) ----
    const float* Qg = g_q + ((size_t)bh * cT + qt * 128) * cD;
#pragma unroll
    for (int it = 0; it < 8; it++) {
        int idx4 = tid + it * 256;          // 0..2047
        int row = idx4 >> 4, c4 = idx4 & 15;
        float4 v = ((const float4*)Qg)[idx4];
        float a[4] = {v.x * 0.125f, v.y * 0.125f, v.z * 0.125f, v.w * 0.125f};
        int base = row * AST + c4 * 4;
#pragma unroll
        for (int j = 0; j < 4; j++) {
            uint32_t hi, lo; split_tf32(a[j], hi, lo);
            QH[base + j] = hi; QL[base + j] = lo;
        }
    }

    float m_i[2] = {-1e30f, -1e30f}, l_i[2] = {0.f, 0.f};
    float O[8][4];
#pragma unroll
    for (int nt = 0; nt < 8; nt++)
#pragma unroll
        for (int c = 0; c < 4; c++) O[nt][c] = 0.f;

    const int ktmax = 2 * qt + 1;
    for (int kt = 0; kt <= ktmax; kt++) {
        __syncthreads();   // prior iter's PV reads done before overwriting K/V (covers Q on iter 0)
        const float* Kg = g_k + ((size_t)bh * cT + kt * 64) * cD;
        const float* VTg = g_vt + (size_t)bh * cD * cT + kt * 64;
#pragma unroll
        for (int it = 0; it < 4; it++) {
            int idx4 = tid + it * 256;       // 0..1023
            int row = idx4 >> 4, c4 = idx4 & 15;
            // K: row-major [key][d]
            float4 kv = ((const float4*)Kg)[idx4];
            int kb = row * AST + c4 * 4;
            { uint32_t h, l; split_tf32(kv.x, h, l); KH[kb + 0] = h; KL[kb + 0] = l; }
            { uint32_t h, l; split_tf32(kv.y, h, l); KH[kb + 1] = h; KL[kb + 1] = l; }
            { uint32_t h, l; split_tf32(kv.z, h, l); KH[kb + 2] = h; KL[kb + 2] = l; }
            { uint32_t h, l; split_tf32(kv.w, h, l); KH[kb + 3] = h; KL[kb + 3] = l; }
            // V: already d-major in gmem (g_vt); row here = d, cols = keys
            float4 vv = *(const float4*)(VTg + (size_t)row * cT + c4 * 4);
            { uint32_t h, l; split_tf32(vv.x, h, l); VH[kb + 0] = h; VL[kb + 0] = l; }
            { uint32_t h, l; split_tf32(vv.y, h, l); VH[kb + 1] = h; VL[kb + 1] = l; }
            { uint32_t h, l; split_tf32(vv.z, h, l); VH[kb + 2] = h; VL[kb + 2] = l; }
            { uint32_t h, l; split_tf32(vv.w, h, l); VH[kb + 3] = h; VL[kb + 3] = l; }
        }
        __syncthreads();

        const bool active = (kt * 64 <= qt * 128 + m0 + 15);
        if (active) {
            // ---- S = Q K^T ----
            float s[8][4];
#pragma unroll
            for (int nt = 0; nt < 8; nt++)
#pragma unroll
                for (int c = 0; c < 4; c++) s[nt][c] = 0.f;

#pragma unroll
            for (int kcp = 0; kcp < 4; kcp++) {
                const int k0 = kcp * 16;
                uint32_t aH0[4], aH1[4], aL0[4], aL1[4];
                ldsm4(qhB + 4u * ((m0 + aRow) * AST + k0 + aCol), aH0);
                ldsm4(qhB + 4u * ((m0 + aRow) * AST + k0 + 8 + aCol), aH1);
                ldsm4(qlB + 4u * ((m0 + aRow) * AST + k0 + aCol), aL0);
                ldsm4(qlB + 4u * ((m0 + aRow) * AST + k0 + 8 + aCol), aL1);
#pragma unroll
                for (int nt = 0; nt < 8; nt++) {
                    uint32_t bh4[4], bl4[4];
                    ldsm4(khB + 4u * ((nt * 8 + bRow) * AST + k0 + bCol), bh4);
                    ldsm4(klB + 4u * ((nt * 8 + bRow) * AST + k0 + bCol), bl4);
                    mma_tf32(s[nt], aH0, bh4);      // Qh.Kh kc0
                    mma_tf32(s[nt], aH1, bh4 + 2);  // Qh.Kh kc1
                    mma_tf32(s[nt], aL0, bh4);      // Ql.Kh kc0
                    mma_tf32(s[nt], aL1, bh4 + 2);
                    mma_tf32(s[nt], aH0, bl4);      // Qh.Kl kc0
                    mma_tf32(s[nt], aH1, bl4 + 2);
                }
            }

            // ---- causal mask (last two tiles only) ----
            if (kt >= 2 * qt) {
                int q0 = qt * 128 + m0 + g, q1 = q0 + 8;
#pragma unroll
                for (int nt = 0; nt < 8; nt++) {
                    int kc0 = kt * 64 + nt * 8 + 2 * l4;
                    if (kc0 > q0) s[nt][0] = -1e30f;
                    if (kc0 + 1 > q0) s[nt][1] = -1e30f;
                    if (kc0 > q1) s[nt][2] = -1e30f;
                    if (kc0 + 1 > q1) s[nt][3] = -1e30f;
                }
            }

            // ---- online softmax (rows g, g+8; row group = 4 lanes sharing g) ----
#pragma unroll
            for (int r = 0; r < 2; r++) {
                float rm = -1e30f;
#pragma unroll
                for (int nt = 0; nt < 8; nt++)
                    rm = fmaxf(rm, fmaxf(s[nt][2 * r], s[nt][2 * r + 1]));
                rm = fmaxf(rm, __shfl_xor_sync(0xffffffffu, rm, 1));
                rm = fmaxf(rm, __shfl_xor_sync(0xffffffffu, rm, 2));
                float mnew = fmaxf(m_i[r], rm);
                float alpha = __expf(m_i[r] - mnew);
                float rs = 0.f;
#pragma unroll
                for (int nt = 0; nt < 8; nt++) {
                    s[nt][2 * r] = __expf(s[nt][2 * r] - mnew);
                    s[nt][2 * r + 1] = __expf(s[nt][2 * r + 1] - mnew);
                    rs += s[nt][2 * r] + s[nt][2 * r + 1];
                }
                rs += __shfl_xor_sync(0xffffffffu, rs, 1);
                rs += __shfl_xor_sync(0xffffffffu, rs, 2);
                l_i[r] = l_i[r] * alpha + rs;
                m_i[r] = mnew;
#pragma unroll
                for (int nt = 0; nt < 8; nt++) {
                    O[nt][2 * r] *= alpha;
                    O[nt][2 * r + 1] *= alpha;
                }
            }

            // ---- stage P (hi/lo) ----
#pragma unroll
            for (int nt = 0; nt < 8; nt++) {
                int col = nt * 8 + 2 * l4;
                uint32_t h0, l0, h1, l1;
                split_tf32(s[nt][0], h0, l0); split_tf32(s[nt][1], h1, l1);
                *(uint2*)&PH[(m0 + g) * AST + col] = make_uint2(h0, h1);
                *(uint2*)&PL[(m0 + g) * AST + col] = make_uint2(l0, l1);
                split_tf32(s[nt][2], h0, l0); split_tf32(s[nt][3], h1, l1);
                *(uint2*)&PH[(m0 + g + 8) * AST + col] = make_uint2(h0, h1);
                *(uint2*)&PL[(m0 + g + 8) * AST + col] = make_uint2(l0, l1);
            }
            __syncwarp();   // P rows are warp-private

            // ---- O += P V ----
#pragma unroll
            for (int kcp = 0; kcp < 4; kcp++) {
                const int k0 = kcp * 16;
                uint32_t pH0[4], pH1[4], pL0[4], pL1[4];
                ldsm4(phB + 4u * ((m0 + aRow) * AST + k0 + aCol), pH0);
                ldsm4(phB + 4u * ((m0 + aRow) * AST + k0 + 8 + aCol), pH1);
                ldsm4(plB + 4u * ((m0 + aRow) * AST + k0 + aCol), pL0);
                ldsm4(plB + 4u * ((m0 + aRow) * AST + k0 + 8 + aCol), pL1);
#pragma unroll
                for (int nt = 0; nt < 8; nt++) {
                    uint32_t vh4[4], vl4[4];
                    ldsm4(vhB + 4u * ((nt * 8 + bRow) * AST + k0 + bCol), vh4);
                    ldsm4(vlB + 4u * ((nt * 8 + bRow) * AST + k0 + bCol), vl4);
                    mma_tf32(O[nt], pH0, vh4);
                    mma_tf32(O[nt], pH1, vh4 + 2);
                    mma_tf32(O[nt], pL0, vh4);
                    mma_tf32(O[nt], pL1, vh4 + 2);
                    mma_tf32(O[nt], pH0, vl4);
                    mma_tf32(O[nt], pH1, vl4 + 2);
                }
            }
        }
    }

    // ---- epilogue ----
    int b = bh >> 4, h = bh & 15;
    float inv0 = 1.0f / l_i[0], inv1 = 1.0f / l_i[1];
    int q0 = qt * 128 + m0 + g;
#pragma unroll
    for (int nt = 0; nt < 8; nt++) {
        int d = h * 64 + nt * 8 + 2 * l4;
        *(float2*)&g_att[((size_t)(b * cT) + q0) * cC + d] =
            make_float2(O[nt][0] * inv0, O[nt][1] * inv0);
        *(float2*)&g_att[((size_t)(b * cT) + q0 + 8) * cC + d] =
            make_float2(O[nt][2] * inv1, O[nt][3] * inv1);
    }
}

// -------------------- launch --------------------
extern "C" void kernel_launch(void* const* d_in, const int* in_sizes, int n_in,
                              void* d_out, int out_size) {
    (void)in_sizes; (void)n_in; (void)out_size;
    const float* x = (const float*)d_in[0];
    const float* w_qkv = (const float*)d_in[1];
    const float* w_out = (const float*)d_in[2];
    float* out = (float*)d_out;

    abssum_partial_kernel<<<1024, 256>>>(w_qkv, cNWq);
    finalize_scale_kernel<<<1, 256>>>(1.0f / (float)cNWq);
    quantize_kernel<0><<<cNWq / 4 / 256, 256>>>(w_qkv, cNWq / 4);
    abssum_partial_kernel<<<1024, 256>>>(w_out, cNWo);
    finalize_scale_kernel<<<1, 256>>>(1.0f / (float)cNWo);
    quantize_kernel<1><<<cNWo / 4 / 256, 256>>>(w_out, cNWo / 4);

    // qkv projection
    {
        cudaFuncSetAttribute(gemm_tf32_kernel<0>,
                             cudaFuncAttributeMaxDynamicSharedMemorySize, GEMM_SMEM_BYTES);
        dim3 grid(cNqkv / 128, cM / 128);
        gemm_tf32_kernel<0><<<grid, 256, GEMM_SMEM_BYTES>>>(x, nullptr);
    }

    // V transpose for attention B-fragments
    {
        dim3 grid(cT / 32, cD / 32, cB * cH);
        transpose_v_kernel<<<grid, dim3(32, 8)>>>();
    }

    // tensor-core causal flash attention
    {
        cudaFuncSetAttribute(flash_attn_tc_kernel,
                             cudaFuncAttributeMaxDynamicSharedMemorySize, ATTN_TC_SMEM);
        dim3 grid(cT / 128, cB * cH);
        flash_attn_tc_kernel<<<grid, 256, ATTN_TC_SMEM>>>();
    }

    // output projection
    {
        cudaFuncSetAttribute(gemm_tf32_kernel<1>,
                             cudaFuncAttributeMaxDynamicSharedMemorySize, GEMM_SMEM_BYTES);
        dim3 grid(cC / 128, cM / 128);
        gemm_tf32_kernel<1><<<grid, 256, GEMM_SMEM_BYTES>>>(nullptr, out);
    }
}

// round 9
// speedup vs baseline: 2.2530x; 1.2135x over previous
#include <cuda_runtime.h>
#include <cuda_bf16.h>
#include <cstdint>

// Problem constants
constexpr int cB = 4;
constexpr int cT = 2048;
constexpr int cC = 1024;
constexpr int cH = 16;
constexpr int cD = 64;
constexpr int cM = cB * cT;          // 8192
constexpr int cNqkv = 3 * cC;        // 3072
constexpr int cNWq = cNqkv * cC;
constexpr int cNWo = cC * cC;
constexpr int cK = 1024;

// -------------------- device scratch --------------------
__device__ float g_partial[1024];
__device__ float g_scale_inv;
__device__ __nv_bfloat16 g_wqb[cNWq];          // ternary qkv weights (bf16, exact)
__device__ __nv_bfloat16 g_wob[cNWo];          // ternary out-proj weights
__device__ __nv_bfloat16 g_xh[cM * cK], g_xl[cM * cK], g_xm[cM * cK];   // x planes
__device__ __nv_bfloat16 g_ah[cM * cK], g_al[cM * cK], g_am[cM * cK];   // attn-out planes
__device__ float g_q[cB * cH * cT * cD];       // [B,H,T,D]
__device__ float g_k[cB * cH * cT * cD];
__device__ float g_v[cB * cH * cT * cD];
__device__ float g_vt[cB * cH * cD * cT];      // V transposed: [B,H,D,T]

// -------------------- absmean scale --------------------
__global__ void abssum_partial_kernel(const float* __restrict__ w, int n) {
    __shared__ float sd[256];
    int chunk = (n + (int)gridDim.x - 1) / (int)gridDim.x;
    int start = (int)blockIdx.x * chunk;
    int end = start + chunk; if (end > n) end = n;
    float s = 0.f;
    for (int i = start + (int)threadIdx.x; i < end; i += 256) s += fabsf(w[i]);
    sd[threadIdx.x] = s;
    __syncthreads();
    for (int o = 128; o > 0; o >>= 1) {
        if ((int)threadIdx.x < o) sd[threadIdx.x] += sd[threadIdx.x + o];
        __syncthreads();
    }
    if (threadIdx.x == 0) g_partial[blockIdx.x] = sd[0];
}

__global__ void finalize_scale_kernel(float inv_n) {
    __shared__ float sd[256];
    float s = 0.f;
    for (int i = threadIdx.x; i < 1024; i += 256) s += g_partial[i];
    sd[threadIdx.x] = s;
    __syncthreads();
    for (int o = 128; o > 0; o >>= 1) {
        if ((int)threadIdx.x < o) sd[threadIdx.x] += sd[threadIdx.x + o];
        __syncthreads();
    }
    if (threadIdx.x == 0) {
        float sc = fmaxf(sd[0] * inv_n, 1e-8f);
        g_scale_inv = 1.0f / sc;
    }
}

template <int WHICH>
__global__ void quantize_kernel(const float* __restrict__ w, int n4) {
    int i = (int)blockIdx.x * 256 + (int)threadIdx.x;
    if (i >= n4) return;
    float inv = g_scale_inv;
    float4 v = ((const float4*)w)[i];
    __nv_bfloat16* dst = (WHICH == 0) ? g_wqb : g_wob;
    __nv_bfloat162* d2 = (__nv_bfloat162*)(dst + (size_t)i * 4);
    d2[0] = __floats2bfloat162_rn(fminf(1.f, fmaxf(-1.f, rintf(v.x * inv))),
                                  fminf(1.f, fmaxf(-1.f, rintf(v.y * inv))));
    d2[1] = __floats2bfloat162_rn(fminf(1.f, fmaxf(-1.f, rintf(v.z * inv))),
                                  fminf(1.f, fmaxf(-1.f, rintf(v.w * inv))));
}

// -------------------- helpers --------------------
__device__ __forceinline__ void cp_async16(uint32_t smem_addr, const void* gptr) {
    asm volatile("cp.async.cg.shared.global [%0], [%1], 16;\n" ::"r"(smem_addr), "l"(gptr));
}
__device__ __forceinline__ void cp_commit() { asm volatile("cp.async.commit_group;\n"); }
template <int N>
__device__ __forceinline__ void cp_wait() { asm volatile("cp.async.wait_group %0;\n" ::"n"(N)); }

__device__ __forceinline__ uint32_t f2tf32(float f) {
    uint32_t u;
    asm("cvt.rna.tf32.f32 %0, %1;\n" : "=r"(u) : "f"(f));
    return u;
}
__device__ __forceinline__ void split_tf32(float v, uint32_t& hi, uint32_t& lo) {
    hi = f2tf32(v);
    lo = f2tf32(v - __uint_as_float(hi));
}
__device__ __forceinline__ void split3_bf16(float a, __nv_bfloat16& h, __nv_bfloat16& l,
                                            __nv_bfloat16& m) {
    h = __float2bfloat16_rn(a);
    float r1 = a - __bfloat162float(h);
    l = __float2bfloat16_rn(r1);
    float r2 = r1 - __bfloat162float(l);
    m = __float2bfloat16_rn(r2);
}
__device__ __forceinline__ void mma_tf32(float* d, const uint32_t* a, const uint32_t* b) {
    asm volatile(
        "mma.sync.aligned.m16n8k8.row.col.f32.tf32.tf32.f32 "
        "{%0,%1,%2,%3}, {%4,%5,%6,%7}, {%8,%9}, {%0,%1,%2,%3};\n"
        : "+f"(d[0]), "+f"(d[1]), "+f"(d[2]), "+f"(d[3])
        : "r"(a[0]), "r"(a[1]), "r"(a[2]), "r"(a[3]), "r"(b[0]), "r"(b[1]));
}
__device__ __forceinline__ void mma_bf16(float* d, const uint32_t* a, const uint32_t* b) {
    asm volatile(
        "mma.sync.aligned.m16n8k16.row.col.f32.bf16.bf16.f32 "
        "{%0,%1,%2,%3}, {%4,%5,%6,%7}, {%8,%9}, {%0,%1,%2,%3};\n"
        : "+f"(d[0]), "+f"(d[1]), "+f"(d[2]), "+f"(d[3])
        : "r"(a[0]), "r"(a[1]), "r"(a[2]), "r"(a[3]), "r"(b[0]), "r"(b[1]));
}
__device__ __forceinline__ void ldsm4(uint32_t addr, uint32_t* r) {
    asm volatile("ldmatrix.sync.aligned.m8n8.x4.shared.b16 {%0,%1,%2,%3}, [%4];\n"
                 : "=r"(r[0]), "=r"(r[1]), "=r"(r[2]), "=r"(r[3]) : "r"(addr));
}

// -------------------- split x into 3 bf16 planes --------------------
__global__ void split_x_kernel(const float* __restrict__ x) {
    int i = (int)blockIdx.x * 256 + (int)threadIdx.x;     // float4 index
    float4 v = ((const float4*)x)[i];
    __nv_bfloat16 h[4], l[4], m[4];
    split3_bf16(v.x, h[0], l[0], m[0]);
    split3_bf16(v.y, h[1], l[1], m[1]);
    split3_bf16(v.z, h[2], l[2], m[2]);
    split3_bf16(v.w, h[3], l[3], m[3]);
    size_t o2 = (size_t)i * 2;
    ((__nv_bfloat162*)g_xh)[o2] = __halves2bfloat162(h[0], h[1]);
    ((__nv_bfloat162*)g_xh)[o2 + 1] = __halves2bfloat162(h[2], h[3]);
    ((__nv_bfloat162*)g_xl)[o2] = __halves2bfloat162(l[0], l[1]);
    ((__nv_bfloat162*)g_xl)[o2 + 1] = __halves2bfloat162(l[2], l[3]);
    ((__nv_bfloat162*)g_xm)[o2] = __halves2bfloat162(m[0], m[1]);
    ((__nv_bfloat162*)g_xm)[o2 + 1] = __halves2bfloat162(m[2], m[3]);
}

// -------------------- bf16 3-plane tensor-core GEMM --------------------
// C[m][n] = sum_k A[m][k]*B[n][k]; A = (h+l+m) bf16 planes, B ternary bf16 (exact)
// CTA 128x128x32, 8 warps 4m x 2n, warp 32x64, mma m16n8k16.
constexpr int ASTR = 40;                      // bf16 row stride (80 B) — LDSM conflict-free
constexpr int APL_B = 128 * ASTR * 2;         // one plane, bytes (10240)
constexpr int STG_B = 3 * APL_B + APL_B;      // A planes + B plane per stage (40960)
constexpr int GEMM_SMEM_BYTES = 2 * STG_B;    // 81920

template <int MODE>
__global__ __launch_bounds__(256) void gemm_bf16_kernel(float* __restrict__ Cparam) {
    extern __shared__ char smc[];
    const __nv_bfloat16* Ah = (MODE == 0) ? g_xh : g_ah;
    const __nv_bfloat16* Al = (MODE == 0) ? g_xl : g_al;
    const __nv_bfloat16* Am = (MODE == 0) ? g_xm : g_am;
    const __nv_bfloat16* Wb = (MODE == 0) ? g_wqb : g_wob;

    const int tid = threadIdx.x;
    const int lane = tid & 31, wid = tid >> 5;
    const int warp_m = (wid >> 1) * 32;
    const int warp_n = (wid & 1) * 64;
    const int g = lane >> 2, l4 = lane & 3;

    const int m0 = (int)blockIdx.y * 128;
    const int n0 = (int)blockIdx.x * 128;

    float acc[2][8][4];
#pragma unroll
    for (int mt = 0; mt < 2; mt++)
#pragma unroll
        for (int nt = 0; nt < 8; nt++)
#pragma unroll
            for (int c = 0; c < 4; c++) acc[mt][nt][c] = 0.f;

    const uint32_t sbase = (uint32_t)__cvta_generic_to_shared(smc);

    // ldmatrix lane address components
    const int aRow = (lane & 7) + ((lane >> 3) & 1) * 8;
    const int aColB = ((lane >> 4) & 1) * 16;              // bytes (8 bf16)
    const int bRow = (lane & 7) + ((lane >> 4) & 1) * 8;
    const int bColB = ((lane >> 3) & 1) * 16;

    auto load_stage = [&](int s) {
        uint32_t stg = sbase + (uint32_t)((s & 1) * STG_B);
        int k0 = s * 32;
#pragma unroll
        for (int i = 0; i < 8; i++) {
            int id = tid + i * 256;               // 0..2047
            if (id < 1536) {                      // A planes
                int p = id >> 9, rem = id & 511;
                int r = rem >> 2, c = rem & 3;
                const __nv_bfloat16* src = (p == 0) ? Ah : (p == 1) ? Al : Am;
                cp_async16(stg + p * APL_B + r * 80 + c * 16,
                           src + (size_t)(m0 + r) * cK + k0 + c * 8);
            } else {                              // B plane
                int id2 = id - 1536;
                int r = id2 >> 2, c = id2 & 3;
                cp_async16(stg + 3 * APL_B + r * 80 + c * 16,
                           Wb + (size_t)(n0 + r) * cK + k0 + c * 8);
            }
        }
        cp_commit();
    };

    const int NS = cK / 32;
    load_stage(0);

    for (int s = 0; s < NS; s++) {
        if (s + 1 < NS) {
            load_stage(s + 1);
            cp_wait<1>();
        } else {
            cp_wait<0>();
        }
        __syncthreads();

        uint32_t stg = sbase + (uint32_t)((s & 1) * STG_B);
        uint32_t bStg = stg + 3 * APL_B;
#pragma unroll
        for (int ks = 0; ks < 2; ks++) {
            const int kB = ks * 32;               // byte offset of k16 step
            uint32_t af[2][3][4];
#pragma unroll
            for (int mt = 0; mt < 2; mt++)
#pragma unroll
                for (int p = 0; p < 3; p++)
                    ldsm4(stg + p * APL_B + (warp_m + mt * 16 + aRow) * 80 + kB + aColB,
                          af[mt][p]);
            uint32_t bf[8][2];
#pragma unroll
            for (int np = 0; np < 4; np++) {
                uint32_t t4[4];
                ldsm4(bStg + (warp_n + np * 16 + bRow) * 80 + kB + bColB, t4);
                bf[2 * np][0] = t4[0]; bf[2 * np][1] = t4[1];
                bf[2 * np + 1][0] = t4[2]; bf[2 * np + 1][1] = t4[3];
            }
#pragma unroll
            for (int mt = 0; mt < 2; mt++)
#pragma unroll
                for (int nt = 0; nt < 8; nt++) {
                    mma_bf16(acc[mt][nt], af[mt][2], bf[nt]);   // m plane (smallest)
                    mma_bf16(acc[mt][nt], af[mt][1], bf[nt]);   // l plane
                    mma_bf16(acc[mt][nt], af[mt][0], bf[nt]);   // h plane
                }
        }
        __syncthreads();
    }

#pragma unroll
    for (int mt = 0; mt < 2; mt++) {
#pragma unroll
        for (int h8 = 0; h8 < 2; h8++) {
            int m = m0 + warp_m + mt * 16 + g + h8 * 8;
#pragma unroll
            for (int nt = 0; nt < 8; nt++) {
                int n = n0 + warp_n + nt * 8 + l4 * 2;
                float2 val = make_float2(acc[mt][nt][h8 * 2 + 0], acc[mt][nt][h8 * 2 + 1]);
                if (MODE == 0) {
                    int b = m >> 11;
                    int t = m & 2047;
                    int part = n >> 10;
                    int c = n & 1023;
                    int hh = c >> 6;
                    int d = c & 63;
                    float* dst = (part == 0) ? g_q : (part == 1) ? g_k : g_v;
                    *(float2*)&dst[((size_t)(b * cH + hh) * cT + t) * cD + d] = val;
                } else {
                    *(float2*)&Cparam[(size_t)m * cC + n] = val;
                }
            }
        }
    }
}

// -------------------- V transpose --------------------
__global__ void transpose_v_kernel() {
    __shared__ float tile[32][33];
    int bh = blockIdx.z;
    int t0 = blockIdx.x * 32, d0 = blockIdx.y * 32;
    int tx = threadIdx.x, ty = threadIdx.y;
#pragma unroll
    for (int i = 0; i < 32; i += 8)
        tile[ty + i][tx] = g_v[((size_t)bh * cT + t0 + ty + i) * cD + d0 + tx];
    __syncthreads();
#pragma unroll
    for (int i = 0; i < 32; i += 8)
        g_vt[((size_t)bh * cD + d0 + ty + i) * cT + t0 + tx] = tile[tx][ty + i];
}

// -------------------- tensor-core flash attention (2xtf32, causal) --------------------
constexpr int AST = 68;
constexpr int QPL = 128 * AST;
constexpr int KPL = 64 * AST;
constexpr int ATTN_TC_SMEM = (2 * QPL + 4 * KPL + 2 * QPL) * 4;   // 208896 B

__global__ __launch_bounds__(256) void flash_attn_tc_kernel() {
    extern __shared__ uint32_t smu[];
    uint32_t* QH = smu;
    uint32_t* QL = QH + QPL;
    uint32_t* KH = QL + QPL;
    uint32_t* KL = KH + KPL;
    uint32_t* VH = KL + KPL;
    uint32_t* VL = VH + KPL;
    uint32_t* PH = VL + KPL;
    uint32_t* PL = PH + QPL;

    const int tid = threadIdx.x;
    const int lane = tid & 31, wid = tid >> 5;
    const int g = lane >> 2, l4 = lane & 3;
    const int bh = blockIdx.y;
    const int qt = (int)gridDim.x - 1 - (int)blockIdx.x;
    const int m0 = wid * 16;

    const uint32_t sbase = (uint32_t)__cvta_generic_to_shared(smu);
    const uint32_t qhB = sbase, qlB = sbase + QPL * 4;
    const uint32_t khB = qlB + QPL * 4, klB = khB + KPL * 4;
    const uint32_t vhB = klB + KPL * 4, vlB = vhB + KPL * 4;
    const uint32_t phB = vlB + KPL * 4, plB = phB + QPL * 4;

    const int aRow = (lane & 7) + ((lane >> 3) & 1) * 8;
    const int aCol = (lane >> 4) * 4;
    const int bRow = lane & 7;
    const int bCol = ((lane >> 3) & 3) * 4;

    const float* Qg = g_q + ((size_t)bh * cT + qt * 128) * cD;
#pragma unroll
    for (int it = 0; it < 8; it++) {
        int idx4 = tid + it * 256;
        int row = idx4 >> 4, c4 = idx4 & 15;
        float4 v = ((const float4*)Qg)[idx4];
        float a[4] = {v.x * 0.125f, v.y * 0.125f, v.z * 0.125f, v.w * 0.125f};
        int base = row * AST + c4 * 4;
#pragma unroll
        for (int j = 0; j < 4; j++) {
            uint32_t hi, lo; split_tf32(a[j], hi, lo);
            QH[base + j] = hi; QL[base + j] = lo;
        }
    }

    float m_i[2] = {-1e30f, -1e30f}, l_i[2] = {0.f, 0.f};
    float O[8][4];
#pragma unroll
    for (int nt = 0; nt < 8; nt++)
#pragma unroll
        for (int c = 0; c < 4; c++) O[nt][c] = 0.f;

    const int ktmax = 2 * qt + 1;
    for (int kt = 0; kt <= ktmax; kt++) {
        __syncthreads();
        const float* Kg = g_k + ((size_t)bh * cT + kt * 64) * cD;
        const float* VTg = g_vt + (size_t)bh * cD * cT + kt * 64;
#pragma unroll
        for (int it = 0; it < 4; it++) {
            int idx4 = tid + it * 256;
            int row = idx4 >> 4, c4 = idx4 & 15;
            float4 kv = ((const float4*)Kg)[idx4];
            int kb = row * AST + c4 * 4;
            { uint32_t h, l; split_tf32(kv.x, h, l); KH[kb + 0] = h; KL[kb + 0] = l; }
            { uint32_t h, l; split_tf32(kv.y, h, l); KH[kb + 1] = h; KL[kb + 1] = l; }
            { uint32_t h, l; split_tf32(kv.z, h, l); KH[kb + 2] = h; KL[kb + 2] = l; }
            { uint32_t h, l; split_tf32(kv.w, h, l); KH[kb + 3] = h; KL[kb + 3] = l; }
            float4 vv = *(const float4*)(VTg + (size_t)row * cT + c4 * 4);
            { uint32_t h, l; split_tf32(vv.x, h, l); VH[kb + 0] = h; VL[kb + 0] = l; }
            { uint32_t h, l; split_tf32(vv.y, h, l); VH[kb + 1] = h; VL[kb + 1] = l; }
            { uint32_t h, l; split_tf32(vv.z, h, l); VH[kb + 2] = h; VL[kb + 2] = l; }
            { uint32_t h, l; split_tf32(vv.w, h, l); VH[kb + 3] = h; VL[kb + 3] = l; }
        }
        __syncthreads();

        const bool active = (kt * 64 <= qt * 128 + m0 + 15);
        if (active) {
            float s[8][4];
#pragma unroll
            for (int nt = 0; nt < 8; nt++)
#pragma unroll
                for (int c = 0; c < 4; c++) s[nt][c] = 0.f;

#pragma unroll
            for (int kcp = 0; kcp < 4; kcp++) {
                const int k0 = kcp * 16;
                uint32_t aH0[4], aH1[4], aL0[4], aL1[4];
                ldsm4(qhB + 4u * ((m0 + aRow) * AST + k0 + aCol), aH0);
                ldsm4(qhB + 4u * ((m0 + aRow) * AST + k0 + 8 + aCol), aH1);
                ldsm4(qlB + 4u * ((m0 + aRow) * AST + k0 + aCol), aL0);
                ldsm4(qlB + 4u * ((m0 + aRow) * AST + k0 + 8 + aCol), aL1);
#pragma unroll
                for (int nt = 0; nt < 8; nt++) {
                    uint32_t bh4[4], bl4[4];
                    ldsm4(khB + 4u * ((nt * 8 + bRow) * AST + k0 + bCol), bh4);
                    ldsm4(klB + 4u * ((nt * 8 + bRow) * AST + k0 + bCol), bl4);
                    mma_tf32(s[nt], aH0, bh4);
                    mma_tf32(s[nt], aH1, bh4 + 2);
                    mma_tf32(s[nt], aL0, bh4);
                    mma_tf32(s[nt], aL1, bh4 + 2);
                    mma_tf32(s[nt], aH0, bl4);
                    mma_tf32(s[nt], aH1, bl4 + 2);
                }
            }

            if (kt >= 2 * qt) {
                int q0 = qt * 128 + m0 + g, q1 = q0 + 8;
#pragma unroll
                for (int nt = 0; nt < 8; nt++) {
                    int kc0 = kt * 64 + nt * 8 + 2 * l4;
                    if (kc0 > q0) s[nt][0] = -1e30f;
                    if (kc0 + 1 > q0) s[nt][1] = -1e30f;
                    if (kc0 > q1) s[nt][2] = -1e30f;
                    if (kc0 + 1 > q1) s[nt][3] = -1e30f;
                }
            }

#pragma unroll
            for (int r = 0; r < 2; r++) {
                float rm = -1e30f;
#pragma unroll
                for (int nt = 0; nt < 8; nt++)
                    rm = fmaxf(rm, fmaxf(s[nt][2 * r], s[nt][2 * r + 1]));
                rm = fmaxf(rm, __shfl_xor_sync(0xffffffffu, rm, 1));
                rm = fmaxf(rm, __shfl_xor_sync(0xffffffffu, rm, 2));
                float mnew = fmaxf(m_i[r], rm);
                float alpha = __expf(m_i[r] - mnew);
                float rs = 0.f;
#pragma unroll
                for (int nt = 0; nt < 8; nt++) {
                    s[nt][2 * r] = __expf(s[nt][2 * r] - mnew);
                    s[nt][2 * r + 1] = __expf(s[nt][2 * r + 1] - mnew);
                    rs += s[nt][2 * r] + s[nt][2 * r + 1];
                }
                rs += __shfl_xor_sync(0xffffffffu, rs, 1);
                rs += __shfl_xor_sync(0xffffffffu, rs, 2);
                l_i[r] = l_i[r] * alpha + rs;
                m_i[r] = mnew;
#pragma unroll
                for (int nt = 0; nt < 8; nt++) {
                    O[nt][2 * r] *= alpha;
                    O[nt][2 * r + 1] *= alpha;
                }
            }

#pragma unroll
            for (int nt = 0; nt < 8; nt++) {
                int col = nt * 8 + 2 * l4;
                uint32_t h0, l0, h1, l1;
                split_tf32(s[nt][0], h0, l0); split_tf32(s[nt][1], h1, l1);
                *(uint2*)&PH[(m0 + g) * AST + col] = make_uint2(h0, h1);
                *(uint2*)&PL[(m0 + g) * AST + col] = make_uint2(l0, l1);
                split_tf32(s[nt][2], h0, l0); split_tf32(s[nt][3], h1, l1);
                *(uint2*)&PH[(m0 + g + 8) * AST + col] = make_uint2(h0, h1);
                *(uint2*)&PL[(m0 + g + 8) * AST + col] = make_uint2(l0, l1);
            }
            __syncwarp();

#pragma unroll
            for (int kcp = 0; kcp < 4; kcp++) {
                const int k0 = kcp * 16;
                uint32_t pH0[4], pH1[4], pL0[4], pL1[4];
                ldsm4(phB + 4u * ((m0 + aRow) * AST + k0 + aCol), pH0);
                ldsm4(phB + 4u * ((m0 + aRow) * AST + k0 + 8 + aCol), pH1);
                ldsm4(plB + 4u * ((m0 + aRow) * AST + k0 + aCol), pL0);
                ldsm4(plB + 4u * ((m0 + aRow) * AST + k0 + 8 + aCol), pL1);
#pragma unroll
                for (int nt = 0; nt < 8; nt++) {
                    uint32_t vh4[4], vl4[4];
                    ldsm4(vhB + 4u * ((nt * 8 + bRow) * AST + k0 + bCol), vh4);
                    ldsm4(vlB + 4u * ((nt * 8 + bRow) * AST + k0 + bCol), vl4);
                    mma_tf32(O[nt], pH0, vh4);
                    mma_tf32(O[nt], pH1, vh4 + 2);
                    mma_tf32(O[nt], pL0, vh4);
                    mma_tf32(O[nt], pL1, vh4 + 2);
                    mma_tf32(O[nt], pH0, vl4);
                    mma_tf32(O[nt], pH1, vl4 + 2);
                }
            }
        }
    }

    // epilogue -> 3 bf16 planes for the output-projection GEMM
    int b = bh >> 4, h = bh & 15;
    float inv0 = 1.0f / l_i[0], inv1 = 1.0f / l_i[1];
    int q0 = qt * 128 + m0 + g;
    size_t row0 = (size_t)(b * cT) + q0;
#pragma unroll
    for (int nt = 0; nt < 8; nt++) {
        int d = h * 64 + nt * 8 + 2 * l4;
        float o0 = O[nt][0] * inv0, o1 = O[nt][1] * inv0;
        float o2 = O[nt][2] * inv1, o3 = O[nt][3] * inv1;
        __nv_bfloat16 h0, l0, mm0, h1, l1, mm1;
        split3_bf16(o0, h0, l0, mm0);
        split3_bf16(o1, h1, l1, mm1);
        *(__nv_bfloat162*)&g_ah[row0 * cC + d] = __halves2bfloat162(h0, h1);
        *(__nv_bfloat162*)&g_al[row0 * cC + d] = __halves2bfloat162(l0, l1);
        *(__nv_bfloat162*)&g_am[row0 * cC + d] = __halves2bfloat162(mm0, mm1);
        split3_bf16(o2, h0, l0, mm0);
        split3_bf16(o3, h1, l1, mm1);
        *(__nv_bfloat162*)&g_ah[(row0 + 8) * cC + d] = __halves2bfloat162(h0, h1);
        *(__nv_bfloat162*)&g_al[(row0 + 8) * cC + d] = __halves2bfloat162(l0, l1);
        *(__nv_bfloat162*)&g_am[(row0 + 8) * cC + d] = __halves2bfloat162(mm0, mm1);
    }
}

// -------------------- launch --------------------
extern "C" void kernel_launch(void* const* d_in, const int* in_sizes, int n_in,
                              void* d_out, int out_size) {
    (void)in_sizes; (void)n_in; (void)out_size;
    const float* x = (const float*)d_in[0];
    const float* w_qkv = (const float*)d_in[1];
    const float* w_out = (const float*)d_in[2];
    float* out = (float*)d_out;

    abssum_partial_kernel<<<1024, 256>>>(w_qkv, cNWq);
    finalize_scale_kernel<<<1, 256>>>(1.0f / (float)cNWq);
    quantize_kernel<0><<<cNWq / 4 / 256, 256>>>(w_qkv, cNWq / 4);
    abssum_partial_kernel<<<1024, 256>>>(w_out, cNWo);
    finalize_scale_kernel<<<1, 256>>>(1.0f / (float)cNWo);
    quantize_kernel<1><<<cNWo / 4 / 256, 256>>>(w_out, cNWo / 4);

    // split x into bf16 planes
    split_x_kernel<<<cM * cK / 4 / 256, 256>>>(x);

    // qkv projection (bf16 3-plane)
    {
        cudaFuncSetAttribute(gemm_bf16_kernel<0>,
                             cudaFuncAttributeMaxDynamicSharedMemorySize, GEMM_SMEM_BYTES);
        dim3 grid(cNqkv / 128, cM / 128);
        gemm_bf16_kernel<0><<<grid, 256, GEMM_SMEM_BYTES>>>(nullptr);
    }

    // V transpose
    {
        dim3 grid(cT / 32, cD / 32, cB * cH);
        transpose_v_kernel<<<grid, dim3(32, 8)>>>();
    }

    // tensor-core causal flash attention (writes att planes)
    {
        cudaFuncSetAttribute(flash_attn_tc_kernel,
                             cudaFuncAttributeMaxDynamicSharedMemorySize, ATTN_TC_SMEM);
        dim3 grid(cT / 128, cB * cH);
        flash_attn_tc_kernel<<<grid, 256, ATTN_TC_SMEM>>>();
    }

    // output projection (bf16 3-plane)
    {
        cudaFuncSetAttribute(gemm_bf16_kernel<1>,
                             cudaFuncAttributeMaxDynamicSharedMemorySize, GEMM_SMEM_BYTES);
        dim3 grid(cC / 128, cM / 128);
        gemm_bf16_kernel<1><<<grid, 256, GEMM_SMEM_BYTES>>>(out);
    }
}

// round 10
// speedup vs baseline: 2.4875x; 1.1041x over previous
#include <cuda_runtime.h>
#include <cuda_bf16.h>
#include <cuda_fp16.h>
#include <cstdint>

// Problem constants
constexpr int cB = 4;
constexpr int cT = 2048;
constexpr int cC = 1024;
constexpr int cH = 16;
constexpr int cD = 64;
constexpr int cM = cB * cT;          // 8192
constexpr int cNqkv = 3 * cC;        // 3072
constexpr int cNWq = cNqkv * cC;
constexpr int cNWo = cC * cC;
constexpr int cK = 1024;

// -------------------- device scratch --------------------
__device__ float g_partial[1024];
__device__ float g_scale_inv;
__device__ __half g_wqh[cNWq];                 // ternary qkv weights (fp16, exact)
__device__ __half g_woh[cNWo];                 // ternary out-proj weights
__device__ __half g_xh[cM * cK], g_xl[cM * cK];   // x planes (fp16 hi/lo)
__device__ __half g_ah[cM * cK], g_al[cM * cK];   // attn-out planes
__device__ float g_q[cB * cH * cT * cD];       // [B,H,T,D]
__device__ float g_k[cB * cH * cT * cD];
__device__ float g_v[cB * cH * cT * cD];
__device__ float g_vt[cB * cH * cD * cT];      // V transposed: [B,H,D,T]

// -------------------- absmean scale --------------------
__global__ void abssum_partial_kernel(const float* __restrict__ w, int n) {
    __shared__ float sd[256];
    int chunk = (n + (int)gridDim.x - 1) / (int)gridDim.x;
    int start = (int)blockIdx.x * chunk;
    int end = start + chunk; if (end > n) end = n;
    float s = 0.f;
    for (int i = start + (int)threadIdx.x; i < end; i += 256) s += fabsf(w[i]);
    sd[threadIdx.x] = s;
    __syncthreads();
    for (int o = 128; o > 0; o >>= 1) {
        if ((int)threadIdx.x < o) sd[threadIdx.x] += sd[threadIdx.x + o];
        __syncthreads();
    }
    if (threadIdx.x == 0) g_partial[blockIdx.x] = sd[0];
}

__global__ void finalize_scale_kernel(float inv_n) {
    __shared__ float sd[256];
    float s = 0.f;
    for (int i = threadIdx.x; i < 1024; i += 256) s += g_partial[i];
    sd[threadIdx.x] = s;
    __syncthreads();
    for (int o = 128; o > 0; o >>= 1) {
        if ((int)threadIdx.x < o) sd[threadIdx.x] += sd[threadIdx.x + o];
        __syncthreads();
    }
    if (threadIdx.x == 0) {
        float sc = fmaxf(sd[0] * inv_n, 1e-8f);
        g_scale_inv = 1.0f / sc;
    }
}

template <int WHICH>
__global__ void quantize_kernel(const float* __restrict__ w, int n4) {
    int i = (int)blockIdx.x * 256 + (int)threadIdx.x;
    if (i >= n4) return;
    float inv = g_scale_inv;
    float4 v = ((const float4*)w)[i];
    __half* dst = (WHICH == 0) ? g_wqh : g_woh;
    __half2* d2 = (__half2*)(dst + (size_t)i * 4);
    d2[0] = __floats2half2_rn(fminf(1.f, fmaxf(-1.f, rintf(v.x * inv))),
                              fminf(1.f, fmaxf(-1.f, rintf(v.y * inv))));
    d2[1] = __floats2half2_rn(fminf(1.f, fmaxf(-1.f, rintf(v.z * inv))),
                              fminf(1.f, fmaxf(-1.f, rintf(v.w * inv))));
}

// -------------------- helpers --------------------
__device__ __forceinline__ void cp_async16(uint32_t smem_addr, const void* gptr) {
    asm volatile("cp.async.cg.shared.global [%0], [%1], 16;\n" ::"r"(smem_addr), "l"(gptr));
}
__device__ __forceinline__ void cp_commit() { asm volatile("cp.async.commit_group;\n"); }
template <int N>
__device__ __forceinline__ void cp_wait() { asm volatile("cp.async.wait_group %0;\n" ::"n"(N)); }

__device__ __forceinline__ uint32_t f2tf32(float f) {
    uint32_t u;
    asm("cvt.rna.tf32.f32 %0, %1;\n" : "=r"(u) : "f"(f));
    return u;
}
__device__ __forceinline__ void split_tf32(float v, uint32_t& hi, uint32_t& lo) {
    hi = f2tf32(v);
    lo = f2tf32(v - __uint_as_float(hi));
}
__device__ __forceinline__ void split2_fp16(float a, __half& h, __half& l) {
    h = __float2half_rn(a);
    l = __float2half_rn(a - __half2float(h));
}
__device__ __forceinline__ void mma_tf32(float* d, const uint32_t* a, const uint32_t* b) {
    asm volatile(
        "mma.sync.aligned.m16n8k8.row.col.f32.tf32.tf32.f32 "
        "{%0,%1,%2,%3}, {%4,%5,%6,%7}, {%8,%9}, {%0,%1,%2,%3};\n"
        : "+f"(d[0]), "+f"(d[1]), "+f"(d[2]), "+f"(d[3])
        : "r"(a[0]), "r"(a[1]), "r"(a[2]), "r"(a[3]), "r"(b[0]), "r"(b[1]));
}
__device__ __forceinline__ void mma_f16(float* d, const uint32_t* a, const uint32_t* b) {
    asm volatile(
        "mma.sync.aligned.m16n8k16.row.col.f32.f16.f16.f32 "
        "{%0,%1,%2,%3}, {%4,%5,%6,%7}, {%8,%9}, {%0,%1,%2,%3};\n"
        : "+f"(d[0]), "+f"(d[1]), "+f"(d[2]), "+f"(d[3])
        : "r"(a[0]), "r"(a[1]), "r"(a[2]), "r"(a[3]), "r"(b[0]), "r"(b[1]));
}
__device__ __forceinline__ void ldsm4(uint32_t addr, uint32_t* r) {
    asm volatile("ldmatrix.sync.aligned.m8n8.x4.shared.b16 {%0,%1,%2,%3}, [%4];\n"
                 : "=r"(r[0]), "=r"(r[1]), "=r"(r[2]), "=r"(r[3]) : "r"(addr));
}

// -------------------- split x into 2 fp16 planes --------------------
__global__ void split_x_kernel(const float* __restrict__ x) {
    int i = (int)blockIdx.x * 256 + (int)threadIdx.x;     // float4 index
    float4 v = ((const float4*)x)[i];
    __half h[4], l[4];
    split2_fp16(v.x, h[0], l[0]);
    split2_fp16(v.y, h[1], l[1]);
    split2_fp16(v.z, h[2], l[2]);
    split2_fp16(v.w, h[3], l[3]);
    size_t o2 = (size_t)i * 2;
    ((__half2*)g_xh)[o2] = __halves2half2(h[0], h[1]);
    ((__half2*)g_xh)[o2 + 1] = __halves2half2(h[2], h[3]);
    ((__half2*)g_xl)[o2] = __halves2half2(l[0], l[1]);
    ((__half2*)g_xl)[o2 + 1] = __halves2half2(l[2], l[3]);
}

// -------------------- fp16 2-plane tensor-core GEMM --------------------
// C[m][n] = sum_k A[m][k]*B[n][k]; A = (h+l) fp16 planes, B ternary fp16 (exact)
// CTA 128x128x32, 8 warps 4m x 2n, warp 32x64, mma m16n8k16.
constexpr int APL_B = 128 * 80;               // one plane, bytes (80 B rows = 40 halves)
constexpr int STG_B = 2 * APL_B + APL_B;      // 2 A planes + B plane (30720)
constexpr int GEMM_SMEM_BYTES = 2 * STG_B;    // 61440

template <int MODE>
__global__ __launch_bounds__(256) void gemm_fp16_kernel(float* __restrict__ Cparam) {
    extern __shared__ char smc[];
    const __half* Ah = (MODE == 0) ? g_xh : g_ah;
    const __half* Al = (MODE == 0) ? g_xl : g_al;
    const __half* Wh = (MODE == 0) ? g_wqh : g_woh;

    const int tid = threadIdx.x;
    const int lane = tid & 31, wid = tid >> 5;
    const int warp_m = (wid >> 1) * 32;
    const int warp_n = (wid & 1) * 64;
    const int g = lane >> 2, l4 = lane & 3;

    const int m0 = (int)blockIdx.y * 128;
    const int n0 = (int)blockIdx.x * 128;

    float acc[2][8][4];
#pragma unroll
    for (int mt = 0; mt < 2; mt++)
#pragma unroll
        for (int nt = 0; nt < 8; nt++)
#pragma unroll
            for (int c = 0; c < 4; c++) acc[mt][nt][c] = 0.f;

    const uint32_t sbase = (uint32_t)__cvta_generic_to_shared(smc);

    const int aRow = (lane & 7) + ((lane >> 3) & 1) * 8;
    const int aColB = ((lane >> 4) & 1) * 16;
    const int bRow = (lane & 7) + ((lane >> 4) & 1) * 8;
    const int bColB = ((lane >> 3) & 1) * 16;

    auto load_stage = [&](int s) {
        uint32_t stg = sbase + (uint32_t)((s & 1) * STG_B);
        int k0 = s * 32;
#pragma unroll
        for (int i = 0; i < 6; i++) {
            int id = tid + i * 256;               // 0..1535
            if (id < 1024) {                      // A planes (2 x 512 chunks)
                int p = id >> 9, rem = id & 511;
                int r = rem >> 2, c = rem & 3;
                const __half* src = (p == 0) ? Ah : Al;
                cp_async16(stg + p * APL_B + r * 80 + c * 16,
                           src + (size_t)(m0 + r) * cK + k0 + c * 8);
            } else {                              // B plane (512 chunks)
                int id2 = id - 1024;
                int r = id2 >> 2, c = id2 & 3;
                cp_async16(stg + 2 * APL_B + r * 80 + c * 16,
                           Wh + (size_t)(n0 + r) * cK + k0 + c * 8);
            }
        }
        cp_commit();
    };

    const int NS = cK / 32;
    load_stage(0);

    for (int s = 0; s < NS; s++) {
        if (s + 1 < NS) {
            load_stage(s + 1);
            cp_wait<1>();
        } else {
            cp_wait<0>();
        }
        __syncthreads();

        uint32_t stg = sbase + (uint32_t)((s & 1) * STG_B);
        uint32_t bStg = stg + 2 * APL_B;
#pragma unroll
        for (int ks = 0; ks < 2; ks++) {
            const int kB = ks * 32;               // byte offset of k16 step
            uint32_t af[2][2][4];
#pragma unroll
            for (int mt = 0; mt < 2; mt++)
#pragma unroll
                for (int p = 0; p < 2; p++)
                    ldsm4(stg + p * APL_B + (warp_m + mt * 16 + aRow) * 80 + kB + aColB,
                          af[mt][p]);
            uint32_t bf[8][2];
#pragma unroll
            for (int np = 0; np < 4; np++) {
                uint32_t t4[4];
                ldsm4(bStg + (warp_n + np * 16 + bRow) * 80 + kB + bColB, t4);
                bf[2 * np][0] = t4[0]; bf[2 * np][1] = t4[1];
                bf[2 * np + 1][0] = t4[2]; bf[2 * np + 1][1] = t4[3];
            }
#pragma unroll
            for (int mt = 0; mt < 2; mt++)
#pragma unroll
                for (int nt = 0; nt < 8; nt++) {
                    mma_f16(acc[mt][nt], af[mt][1], bf[nt]);   // lo plane
                    mma_f16(acc[mt][nt], af[mt][0], bf[nt]);   // hi plane
                }
        }
        __syncthreads();
    }

#pragma unroll
    for (int mt = 0; mt < 2; mt++) {
#pragma unroll
        for (int h8 = 0; h8 < 2; h8++) {
            int m = m0 + warp_m + mt * 16 + g + h8 * 8;
#pragma unroll
            for (int nt = 0; nt < 8; nt++) {
                int n = n0 + warp_n + nt * 8 + l4 * 2;
                float2 val = make_float2(acc[mt][nt][h8 * 2 + 0], acc[mt][nt][h8 * 2 + 1]);
                if (MODE == 0) {
                    int b = m >> 11;
                    int t = m & 2047;
                    int part = n >> 10;
                    int c = n & 1023;
                    int hh = c >> 6;
                    int d = c & 63;
                    float* dst = (part == 0) ? g_q : (part == 1) ? g_k : g_v;
                    *(float2*)&dst[((size_t)(b * cH + hh) * cT + t) * cD + d] = val;
                } else {
                    *(float2*)&Cparam[(size_t)m * cC + n] = val;
                }
            }
        }
    }
}

// -------------------- V transpose --------------------
__global__ void transpose_v_kernel() {
    __shared__ float tile[32][33];
    int bh = blockIdx.z;
    int t0 = blockIdx.x * 32, d0 = blockIdx.y * 32;
    int tx = threadIdx.x, ty = threadIdx.y;
#pragma unroll
    for (int i = 0; i < 32; i += 8)
        tile[ty + i][tx] = g_v[((size_t)bh * cT + t0 + ty + i) * cD + d0 + tx];
    __syncthreads();
#pragma unroll
    for (int i = 0; i < 32; i += 8)
        g_vt[((size_t)bh * cD + d0 + ty + i) * cT + t0 + tx] = tile[tx][ty + i];
}

// -------------------- tensor-core flash attention (2xtf32, causal) --------------------
constexpr int AST = 68;
constexpr int QPL = 128 * AST;
constexpr int KPL = 64 * AST;
constexpr int ATTN_TC_SMEM = (2 * QPL + 4 * KPL + 2 * QPL) * 4;   // 208896 B

__global__ __launch_bounds__(256) void flash_attn_tc_kernel() {
    extern __shared__ uint32_t smu[];
    uint32_t* QH = smu;
    uint32_t* QL = QH + QPL;
    uint32_t* KH = QL + QPL;
    uint32_t* KL = KH + KPL;
    uint32_t* VH = KL + KPL;
    uint32_t* VL = VH + KPL;
    uint32_t* PH = VL + KPL;
    uint32_t* PL = PH + QPL;

    const int tid = threadIdx.x;
    const int lane = tid & 31, wid = tid >> 5;
    const int g = lane >> 2, l4 = lane & 3;
    const int bh = blockIdx.y;
    const int qt = (int)gridDim.x - 1 - (int)blockIdx.x;
    const int m0 = wid * 16;

    const uint32_t sbase = (uint32_t)__cvta_generic_to_shared(smu);
    const uint32_t qhB = sbase, qlB = sbase + QPL * 4;
    const uint32_t khB = qlB + QPL * 4, klB = khB + KPL * 4;
    const uint32_t vhB = klB + KPL * 4, vlB = vhB + KPL * 4;
    const uint32_t phB = vlB + KPL * 4, plB = phB + QPL * 4;

    const int aRow = (lane & 7) + ((lane >> 3) & 1) * 8;
    const int aCol = (lane >> 4) * 4;
    const int bRow = lane & 7;
    const int bCol = ((lane >> 3) & 3) * 4;

    const float* Qg = g_q + ((size_t)bh * cT + qt * 128) * cD;
#pragma unroll
    for (int it = 0; it < 8; it++) {
        int idx4 = tid + it * 256;
        int row = idx4 >> 4, c4 = idx4 & 15;
        float4 v = ((const float4*)Qg)[idx4];
        float a[4] = {v.x * 0.125f, v.y * 0.125f, v.z * 0.125f, v.w * 0.125f};
        int base = row * AST + c4 * 4;
#pragma unroll
        for (int j = 0; j < 4; j++) {
            uint32_t hi, lo; split_tf32(a[j], hi, lo);
            QH[base + j] = hi; QL[base + j] = lo;
        }
    }

    float m_i[2] = {-1e30f, -1e30f}, l_i[2] = {0.f, 0.f};
    float O[8][4];
#pragma unroll
    for (int nt = 0; nt < 8; nt++)
#pragma unroll
        for (int c = 0; c < 4; c++) O[nt][c] = 0.f;

    const int ktmax = 2 * qt + 1;
    for (int kt = 0; kt <= ktmax; kt++) {
        __syncthreads();
        const float* Kg = g_k + ((size_t)bh * cT + kt * 64) * cD;
        const float* VTg = g_vt + (size_t)bh * cD * cT + kt * 64;
#pragma unroll
        for (int it = 0; it < 4; it++) {
            int idx4 = tid + it * 256;
            int row = idx4 >> 4, c4 = idx4 & 15;
            float4 kv = ((const float4*)Kg)[idx4];
            int kb = row * AST + c4 * 4;
            { uint32_t h, l; split_tf32(kv.x, h, l); KH[kb + 0] = h; KL[kb + 0] = l; }
            { uint32_t h, l; split_tf32(kv.y, h, l); KH[kb + 1] = h; KL[kb + 1] = l; }
            { uint32_t h, l; split_tf32(kv.z, h, l); KH[kb + 2] = h; KL[kb + 2] = l; }
            { uint32_t h, l; split_tf32(kv.w, h, l); KH[kb + 3] = h; KL[kb + 3] = l; }
            float4 vv = *(const float4*)(VTg + (size_t)row * cT + c4 * 4);
            { uint32_t h, l; split_tf32(vv.x, h, l); VH[kb + 0] = h; VL[kb + 0] = l; }
            { uint32_t h, l; split_tf32(vv.y, h, l); VH[kb + 1] = h; VL[kb + 1] = l; }
            { uint32_t h, l; split_tf32(vv.z, h, l); VH[kb + 2] = h; VL[kb + 2] = l; }
            { uint32_t h, l; split_tf32(vv.w, h, l); VH[kb + 3] = h; VL[kb + 3] = l; }
        }
        __syncthreads();

        const bool active = (kt * 64 <= qt * 128 + m0 + 15);
        if (active) {
            float s[8][4];
#pragma unroll
            for (int nt = 0; nt < 8; nt++)
#pragma unroll
                for (int c = 0; c < 4; c++) s[nt][c] = 0.f;

#pragma unroll
            for (int kcp = 0; kcp < 4; kcp++) {
                const int k0 = kcp * 16;
                uint32_t aH0[4], aH1[4], aL0[4], aL1[4];
                ldsm4(qhB + 4u * ((m0 + aRow) * AST + k0 + aCol), aH0);
                ldsm4(qhB + 4u * ((m0 + aRow) * AST + k0 + 8 + aCol), aH1);
                ldsm4(qlB + 4u * ((m0 + aRow) * AST + k0 + aCol), aL0);
                ldsm4(qlB + 4u * ((m0 + aRow) * AST + k0 + 8 + aCol), aL1);
#pragma unroll
                for (int nt = 0; nt < 8; nt++) {
                    uint32_t bh4[4], bl4[4];
                    ldsm4(khB + 4u * ((nt * 8 + bRow) * AST + k0 + bCol), bh4);
                    ldsm4(klB + 4u * ((nt * 8 + bRow) * AST + k0 + bCol), bl4);
                    mma_tf32(s[nt], aH0, bh4);
                    mma_tf32(s[nt], aH1, bh4 + 2);
                    mma_tf32(s[nt], aL0, bh4);
                    mma_tf32(s[nt], aL1, bh4 + 2);
                    mma_tf32(s[nt], aH0, bl4);
                    mma_tf32(s[nt], aH1, bl4 + 2);
                }
            }

            if (kt >= 2 * qt) {
                int q0 = qt * 128 + m0 + g, q1 = q0 + 8;
#pragma unroll
                for (int nt = 0; nt < 8; nt++) {
                    int kc0 = kt * 64 + nt * 8 + 2 * l4;
                    if (kc0 > q0) s[nt][0] = -1e30f;
                    if (kc0 + 1 > q0) s[nt][1] = -1e30f;
                    if (kc0 > q1) s[nt][2] = -1e30f;
                    if (kc0 + 1 > q1) s[nt][3] = -1e30f;
                }
            }

#pragma unroll
            for (int r = 0; r < 2; r++) {
                float rm = -1e30f;
#pragma unroll
                for (int nt = 0; nt < 8; nt++)
                    rm = fmaxf(rm, fmaxf(s[nt][2 * r], s[nt][2 * r + 1]));
                rm = fmaxf(rm, __shfl_xor_sync(0xffffffffu, rm, 1));
                rm = fmaxf(rm, __shfl_xor_sync(0xffffffffu, rm, 2));
                float mnew = fmaxf(m_i[r], rm);
                float alpha = __expf(m_i[r] - mnew);
                float rs = 0.f;
#pragma unroll
                for (int nt = 0; nt < 8; nt++) {
                    s[nt][2 * r] = __expf(s[nt][2 * r] - mnew);
                    s[nt][2 * r + 1] = __expf(s[nt][2 * r + 1] - mnew);
                    rs += s[nt][2 * r] + s[nt][2 * r + 1];
                }
                rs += __shfl_xor_sync(0xffffffffu, rs, 1);
                rs += __shfl_xor_sync(0xffffffffu, rs, 2);
                l_i[r] = l_i[r] * alpha + rs;
                m_i[r] = mnew;
#pragma unroll
                for (int nt = 0; nt < 8; nt++) {
                    O[nt][2 * r] *= alpha;
                    O[nt][2 * r + 1] *= alpha;
                }
            }

#pragma unroll
            for (int nt = 0; nt < 8; nt++) {
                int col = nt * 8 + 2 * l4;
                uint32_t h0, l0, h1, l1;
                split_tf32(s[nt][0], h0, l0); split_tf32(s[nt][1], h1, l1);
                *(uint2*)&PH[(m0 + g) * AST + col] = make_uint2(h0, h1);
                *(uint2*)&PL[(m0 + g) * AST + col] = make_uint2(l0, l1);
                split_tf32(s[nt][2], h0, l0); split_tf32(s[nt][3], h1, l1);
                *(uint2*)&PH[(m0 + g + 8) * AST + col] = make_uint2(h0, h1);
                *(uint2*)&PL[(m0 + g + 8) * AST + col] = make_uint2(l0, l1);
            }
            __syncwarp();

#pragma unroll
            for (int kcp = 0; kcp < 4; kcp++) {
                const int k0 = kcp * 16;
                uint32_t pH0[4], pH1[4], pL0[4], pL1[4];
                ldsm4(phB + 4u * ((m0 + aRow) * AST + k0 + aCol), pH0);
                ldsm4(phB + 4u * ((m0 + aRow) * AST + k0 + 8 + aCol), pH1);
                ldsm4(plB + 4u * ((m0 + aRow) * AST + k0 + aCol), pL0);
                ldsm4(plB + 4u * ((m0 + aRow) * AST + k0 + 8 + aCol), pL1);
#pragma unroll
                for (int nt = 0; nt < 8; nt++) {
                    uint32_t vh4[4], vl4[4];
                    ldsm4(vhB + 4u * ((nt * 8 + bRow) * AST + k0 + bCol), vh4);
                    ldsm4(vlB + 4u * ((nt * 8 + bRow) * AST + k0 + bCol), vl4);
                    mma_tf32(O[nt], pH0, vh4);
                    mma_tf32(O[nt], pH1, vh4 + 2);
                    mma_tf32(O[nt], pL0, vh4);
                    mma_tf32(O[nt], pL1, vh4 + 2);
                    mma_tf32(O[nt], pH0, vl4);
                    mma_tf32(O[nt], pH1, vl4 + 2);
                }
            }
        }
    }

    // epilogue -> 2 fp16 planes for the output-projection GEMM
    int b = bh >> 4, h = bh & 15;
    float inv0 = 1.0f / l_i[0], inv1 = 1.0f / l_i[1];
    int q0 = qt * 128 + m0 + g;
    size_t row0 = (size_t)(b * cT) + q0;
#pragma unroll
    for (int nt = 0; nt < 8; nt++) {
        int d = h * 64 + nt * 8 + 2 * l4;
        float o0 = O[nt][0] * inv0, o1 = O[nt][1] * inv0;
        float o2 = O[nt][2] * inv1, o3 = O[nt][3] * inv1;
        __half h0, l0, h1, l1;
        split2_fp16(o0, h0, l0);
        split2_fp16(o1, h1, l1);
        *(__half2*)&g_ah[row0 * cC + d] = __halves2half2(h0, h1);
        *(__half2*)&g_al[row0 * cC + d] = __halves2half2(l0, l1);
        split2_fp16(o2, h0, l0);
        split2_fp16(o3, h1, l1);
        *(__half2*)&g_ah[(row0 + 8) * cC + d] = __halves2half2(h0, h1);
        *(__half2*)&g_al[(row0 + 8) * cC + d] = __halves2half2(l0, l1);
    }
}

// -------------------- launch --------------------
extern "C" void kernel_launch(void* const* d_in, const int* in_sizes, int n_in,
                              void* d_out, int out_size) {
    (void)in_sizes; (void)n_in; (void)out_size;
    const float* x = (const float*)d_in[0];
    const float* w_qkv = (const float*)d_in[1];
    const float* w_out = (const float*)d_in[2];
    float* out = (float*)d_out;

    abssum_partial_kernel<<<1024, 256>>>(w_qkv, cNWq);
    finalize_scale_kernel<<<1, 256>>>(1.0f / (float)cNWq);
    quantize_kernel<0><<<cNWq / 4 / 256, 256>>>(w_qkv, cNWq / 4);
    abssum_partial_kernel<<<1024, 256>>>(w_out, cNWo);
    finalize_scale_kernel<<<1, 256>>>(1.0f / (float)cNWo);
    quantize_kernel<1><<<cNWo / 4 / 256, 256>>>(w_out, cNWo / 4);

    // split x into fp16 planes
    split_x_kernel<<<cM * cK / 4 / 256, 256>>>(x);

    // qkv projection (fp16 2-plane)
    {
        cudaFuncSetAttribute(gemm_fp16_kernel<0>,
                             cudaFuncAttributeMaxDynamicSharedMemorySize, GEMM_SMEM_BYTES);
        dim3 grid(cNqkv / 128, cM / 128);
        gemm_fp16_kernel<0><<<grid, 256, GEMM_SMEM_BYTES>>>(nullptr);
    }

    // V transpose
    {
        dim3 grid(cT / 32, cD / 32, cB * cH);
        transpose_v_kernel<<<grid, dim3(32, 8)>>>();
    }

    // tensor-core causal flash attention (writes att planes)
    {
        cudaFuncSetAttribute(flash_attn_tc_kernel,
                             cudaFuncAttributeMaxDynamicSharedMemorySize, ATTN_TC_SMEM);
        dim3 grid(cT / 128, cB * cH);
        flash_attn_tc_kernel<<<grid, 256, ATTN_TC_SMEM>>>();
    }

    // output projection (fp16 2-plane)
    {
        cudaFuncSetAttribute(gemm_fp16_kernel<1>,
                             cudaFuncAttributeMaxDynamicSharedMemorySize, GEMM_SMEM_BYTES);
        dim3 grid(cC / 128, cM / 128);
        gemm_fp16_kernel<1><<<grid, 256, GEMM_SMEM_BYTES>>>(out);
    }
}

// round 11
// speedup vs baseline: 3.4655x; 1.3932x over previous
#include <cuda_runtime.h>
#include <cuda_fp16.h>
#include <cstdint>

// Problem constants
constexpr int cB = 4;
constexpr int cT = 2048;
constexpr int cC = 1024;
constexpr int cH = 16;
constexpr int cD = 64;
constexpr int cM = cB * cT;          // 8192
constexpr int cNqkv = 3 * cC;        // 3072
constexpr int cNWq = cNqkv * cC;
constexpr int cNWo = cC * cC;
constexpr int cK = 1024;

// -------------------- device scratch --------------------
__device__ float g_partial[1024];
__device__ float g_scale_inv;
__device__ __half g_wqh[cNWq];                 // ternary qkv weights (fp16, exact)
__device__ __half g_woh[cNWo];                 // ternary out-proj weights
__device__ __half g_xh[cM * cK], g_xl[cM * cK];   // x planes (fp16 hi/lo)
__device__ __half g_ah[cM * cK], g_al[cM * cK];   // attn-out planes
__device__ float g_q[cB * cH * cT * cD];       // [B,H,T,D]
__device__ float g_k[cB * cH * cT * cD];
__device__ float g_v[cB * cH * cT * cD];
__device__ float g_vt[cB * cH * cD * cT];      // V transposed: [B,H,D,T]

// -------------------- absmean scale --------------------
__global__ void abssum_partial_kernel(const float* __restrict__ w, int n) {
    __shared__ float sd[256];
    int chunk = (n + (int)gridDim.x - 1) / (int)gridDim.x;
    int start = (int)blockIdx.x * chunk;
    int end = start + chunk; if (end > n) end = n;
    float s = 0.f;
    for (int i = start + (int)threadIdx.x; i < end; i += 256) s += fabsf(w[i]);
    sd[threadIdx.x] = s;
    __syncthreads();
    for (int o = 128; o > 0; o >>= 1) {
        if ((int)threadIdx.x < o) sd[threadIdx.x] += sd[threadIdx.x + o];
        __syncthreads();
    }
    if (threadIdx.x == 0) g_partial[blockIdx.x] = sd[0];
}

__global__ void finalize_scale_kernel(float inv_n) {
    __shared__ float sd[256];
    float s = 0.f;
    for (int i = threadIdx.x; i < 1024; i += 256) s += g_partial[i];
    sd[threadIdx.x] = s;
    __syncthreads();
    for (int o = 128; o > 0; o >>= 1) {
        if ((int)threadIdx.x < o) sd[threadIdx.x] += sd[threadIdx.x + o];
        __syncthreads();
    }
    if (threadIdx.x == 0) {
        float sc = fmaxf(sd[0] * inv_n, 1e-8f);
        g_scale_inv = 1.0f / sc;
    }
}

template <int WHICH>
__global__ void quantize_kernel(const float* __restrict__ w, int n4) {
    int i = (int)blockIdx.x * 256 + (int)threadIdx.x;
    if (i >= n4) return;
    float inv = g_scale_inv;
    float4 v = ((const float4*)w)[i];
    __half* dst = (WHICH == 0) ? g_wqh : g_woh;
    __half2* d2 = (__half2*)(dst + (size_t)i * 4);
    d2[0] = __floats2half2_rn(fminf(1.f, fmaxf(-1.f, rintf(v.x * inv))),
                              fminf(1.f, fmaxf(-1.f, rintf(v.y * inv))));
    d2[1] = __floats2half2_rn(fminf(1.f, fmaxf(-1.f, rintf(v.z * inv))),
                              fminf(1.f, fmaxf(-1.f, rintf(v.w * inv))));
}

// -------------------- helpers --------------------
__device__ __forceinline__ void cp_async16(uint32_t smem_addr, const void* gptr) {
    asm volatile("cp.async.cg.shared.global [%0], [%1], 16;\n" ::"r"(smem_addr), "l"(gptr));
}
__device__ __forceinline__ void cp_commit() { asm volatile("cp.async.commit_group;\n"); }
template <int N>
__device__ __forceinline__ void cp_wait() { asm volatile("cp.async.wait_group %0;\n" ::"n"(N)); }

__device__ __forceinline__ void split2_fp16(float a, __half& h, __half& l) {
    h = __float2half_rn(a);
    l = __float2half_rn(a - __half2float(h));
}
__device__ __forceinline__ void mma_f16(float* d, const uint32_t* a, const uint32_t* b) {
    asm volatile(
        "mma.sync.aligned.m16n8k16.row.col.f32.f16.f16.f32 "
        "{%0,%1,%2,%3}, {%4,%5,%6,%7}, {%8,%9}, {%0,%1,%2,%3};\n"
        : "+f"(d[0]), "+f"(d[1]), "+f"(d[2]), "+f"(d[3])
        : "r"(a[0]), "r"(a[1]), "r"(a[2]), "r"(a[3]), "r"(b[0]), "r"(b[1]));
}
__device__ __forceinline__ void ldsm4(uint32_t addr, uint32_t* r) {
    asm volatile("ldmatrix.sync.aligned.m8n8.x4.shared.b16 {%0,%1,%2,%3}, [%4];\n"
                 : "=r"(r[0]), "=r"(r[1]), "=r"(r[2]), "=r"(r[3]) : "r"(addr));
}

// -------------------- split x into 2 fp16 planes --------------------
__global__ void split_x_kernel(const float* __restrict__ x) {
    int i = (int)blockIdx.x * 256 + (int)threadIdx.x;     // float4 index
    float4 v = ((const float4*)x)[i];
    __half h[4], l[4];
    split2_fp16(v.x, h[0], l[0]);
    split2_fp16(v.y, h[1], l[1]);
    split2_fp16(v.z, h[2], l[2]);
    split2_fp16(v.w, h[3], l[3]);
    size_t o2 = (size_t)i * 2;
    ((__half2*)g_xh)[o2] = __halves2half2(h[0], h[1]);
    ((__half2*)g_xh)[o2 + 1] = __halves2half2(h[2], h[3]);
    ((__half2*)g_xl)[o2] = __halves2half2(l[0], l[1]);
    ((__half2*)g_xl)[o2 + 1] = __halves2half2(l[2], l[3]);
}

// -------------------- fp16 2-plane tensor-core GEMM --------------------
constexpr int APL_B = 128 * 80;               // one plane, bytes
constexpr int STG_B = 2 * APL_B + APL_B;      // 30720
constexpr int GEMM_SMEM_BYTES = 2 * STG_B;    // 61440

template <int MODE>
__global__ __launch_bounds__(256) void gemm_fp16_kernel(float* __restrict__ Cparam) {
    extern __shared__ char smc[];
    const __half* Ah = (MODE == 0) ? g_xh : g_ah;
    const __half* Al = (MODE == 0) ? g_xl : g_al;
    const __half* Wh = (MODE == 0) ? g_wqh : g_woh;

    const int tid = threadIdx.x;
    const int lane = tid & 31, wid = tid >> 5;
    const int warp_m = (wid >> 1) * 32;
    const int warp_n = (wid & 1) * 64;
    const int g = lane >> 2, l4 = lane & 3;

    const int m0 = (int)blockIdx.y * 128;
    const int n0 = (int)blockIdx.x * 128;

    float acc[2][8][4];
#pragma unroll
    for (int mt = 0; mt < 2; mt++)
#pragma unroll
        for (int nt = 0; nt < 8; nt++)
#pragma unroll
            for (int c = 0; c < 4; c++) acc[mt][nt][c] = 0.f;

    const uint32_t sbase = (uint32_t)__cvta_generic_to_shared(smc);

    const int aRow = (lane & 7) + ((lane >> 3) & 1) * 8;
    const int aColB = ((lane >> 4) & 1) * 16;
    const int bRow = (lane & 7) + ((lane >> 4) & 1) * 8;
    const int bColB = ((lane >> 3) & 1) * 16;

    auto load_stage = [&](int s) {
        uint32_t stg = sbase + (uint32_t)((s & 1) * STG_B);
        int k0 = s * 32;
#pragma unroll
        for (int i = 0; i < 6; i++) {
            int id = tid + i * 256;
            if (id < 1024) {
                int p = id >> 9, rem = id & 511;
                int r = rem >> 2, c = rem & 3;
                const __half* src = (p == 0) ? Ah : Al;
                cp_async16(stg + p * APL_B + r * 80 + c * 16,
                           src + (size_t)(m0 + r) * cK + k0 + c * 8);
            } else {
                int id2 = id - 1024;
                int r = id2 >> 2, c = id2 & 3;
                cp_async16(stg + 2 * APL_B + r * 80 + c * 16,
                           Wh + (size_t)(n0 + r) * cK + k0 + c * 8);
            }
        }
        cp_commit();
    };

    const int NS = cK / 32;
    load_stage(0);

    for (int s = 0; s < NS; s++) {
        if (s + 1 < NS) {
            load_stage(s + 1);
            cp_wait<1>();
        } else {
            cp_wait<0>();
        }
        __syncthreads();

        uint32_t stg = sbase + (uint32_t)((s & 1) * STG_B);
        uint32_t bStg = stg + 2 * APL_B;
#pragma unroll
        for (int ks = 0; ks < 2; ks++) {
            const int kB = ks * 32;
            uint32_t af[2][2][4];
#pragma unroll
            for (int mt = 0; mt < 2; mt++)
#pragma unroll
                for (int p = 0; p < 2; p++)
                    ldsm4(stg + p * APL_B + (warp_m + mt * 16 + aRow) * 80 + kB + aColB,
                          af[mt][p]);
            uint32_t bf[8][2];
#pragma unroll
            for (int np = 0; np < 4; np++) {
                uint32_t t4[4];
                ldsm4(bStg + (warp_n + np * 16 + bRow) * 80 + kB + bColB, t4);
                bf[2 * np][0] = t4[0]; bf[2 * np][1] = t4[1];
                bf[2 * np + 1][0] = t4[2]; bf[2 * np + 1][1] = t4[3];
            }
#pragma unroll
            for (int mt = 0; mt < 2; mt++)
#pragma unroll
                for (int nt = 0; nt < 8; nt++) {
                    mma_f16(acc[mt][nt], af[mt][1], bf[nt]);
                    mma_f16(acc[mt][nt], af[mt][0], bf[nt]);
                }
        }
        __syncthreads();
    }

#pragma unroll
    for (int mt = 0; mt < 2; mt++) {
#pragma unroll
        for (int h8 = 0; h8 < 2; h8++) {
            int m = m0 + warp_m + mt * 16 + g + h8 * 8;
#pragma unroll
            for (int nt = 0; nt < 8; nt++) {
                int n = n0 + warp_n + nt * 8 + l4 * 2;
                float2 val = make_float2(acc[mt][nt][h8 * 2 + 0], acc[mt][nt][h8 * 2 + 1]);
                if (MODE == 0) {
                    int b = m >> 11;
                    int t = m & 2047;
                    int part = n >> 10;
                    int c = n & 1023;
                    int hh = c >> 6;
                    int d = c & 63;
                    float* dst = (part == 0) ? g_q : (part == 1) ? g_k : g_v;
                    *(float2*)&dst[((size_t)(b * cH + hh) * cT + t) * cD + d] = val;
                } else {
                    *(float2*)&Cparam[(size_t)m * cC + n] = val;
                }
            }
        }
    }
}

// -------------------- V transpose --------------------
__global__ void transpose_v_kernel() {
    __shared__ float tile[32][33];
    int bh = blockIdx.z;
    int t0 = blockIdx.x * 32, d0 = blockIdx.y * 32;
    int tx = threadIdx.x, ty = threadIdx.y;
#pragma unroll
    for (int i = 0; i < 32; i += 8)
        tile[ty + i][tx] = g_v[((size_t)bh * cT + t0 + ty + i) * cD + d0 + tx];
    __syncthreads();
#pragma unroll
    for (int i = 0; i < 32; i += 8)
        g_vt[((size_t)bh * cD + d0 + ty + i) * cT + t0 + tx] = tile[tx][ty + i];
}

// -------------------- fp16 2-plane tensor-core flash attention (causal) --------------------
// CTA: 128 q-rows, 8 warps x 16 rows; K-tile 64. fp16 hi/lo planes, m16n8k16.
constexpr int HST = 72;                        // half stride per row (144 B)
constexpr int QPL2 = 128 * HST;                // halves
constexpr int KPL2 = 64 * HST;
constexpr int ATTN_SMEM = (2 * QPL2 + 4 * KPL2 + 2 * QPL2) * 2;   // 110592 B

__global__ __launch_bounds__(256) void flash_attn_f16_kernel() {
    extern __shared__ __half smh[];
    __half* QH = smh;
    __half* QL = QH + QPL2;
    __half* KH = QL + QPL2;
    __half* KL = KH + KPL2;
    __half* VH = KL + KPL2;
    __half* VL = VH + KPL2;
    __half* PH = VL + KPL2;
    __half* PL = PH + QPL2;

    const int tid = threadIdx.x;
    const int lane = tid & 31, wid = tid >> 5;
    const int g = lane >> 2, l4 = lane & 3;
    const int bh = blockIdx.y;
    const int qt = (int)gridDim.x - 1 - (int)blockIdx.x;   // big tiles first
    const int m0 = wid * 16;

    const uint32_t sbase = (uint32_t)__cvta_generic_to_shared(smh);
    const uint32_t qhB = sbase, qlB = sbase + QPL2 * 2;
    const uint32_t khB = qlB + QPL2 * 2, klB = khB + KPL2 * 2;
    const uint32_t vhB = klB + KPL2 * 2, vlB = vhB + KPL2 * 2;
    const uint32_t phB = vlB + KPL2 * 2, plB = phB + QPL2 * 2;

    // fragment lane addressing (verified in gemm_fp16_kernel)
    const int aRow = (lane & 7) + ((lane >> 3) & 1) * 8;
    const int aColB = ((lane >> 4) & 1) * 16;
    const int bRow = (lane & 7) + ((lane >> 4) & 1) * 8;
    const int bColB = ((lane >> 3) & 1) * 16;

    // ---- load + split Q (pre-scaled by 1/8) ----
    const float* Qg = g_q + ((size_t)bh * cT + qt * 128) * cD;
#pragma unroll
    for (int it = 0; it < 8; it++) {
        int idx4 = tid + it * 256;            // 0..2047
        int row = idx4 >> 4, c4 = idx4 & 15;
        float4 v = ((const float4*)Qg)[idx4];
        __half h0, l0, h1, l1, h2, l2, h3, l3;
        split2_fp16(v.x * 0.125f, h0, l0);
        split2_fp16(v.y * 0.125f, h1, l1);
        split2_fp16(v.z * 0.125f, h2, l2);
        split2_fp16(v.w * 0.125f, h3, l3);
        int base = row * HST + c4 * 4;
        *(__half2*)&QH[base] = __halves2half2(h0, h1);
        *(__half2*)&QH[base + 2] = __halves2half2(h2, h3);
        *(__half2*)&QL[base] = __halves2half2(l0, l1);
        *(__half2*)&QL[base + 2] = __halves2half2(l2, l3);
    }

    float m_i[2] = {-1e30f, -1e30f}, l_i[2] = {0.f, 0.f};
    float O[8][4];
#pragma unroll
    for (int nt = 0; nt < 8; nt++)
#pragma unroll
        for (int c = 0; c < 4; c++) O[nt][c] = 0.f;

    const int ktmax = 2 * qt + 1;
    for (int kt = 0; kt <= ktmax; kt++) {
        __syncthreads();   // prior PV reads done before overwriting K/V (covers Q on iter 0)
        const float* Kg = g_k + ((size_t)bh * cT + kt * 64) * cD;
        const float* VTg = g_vt + (size_t)bh * cD * cT + kt * 64;
#pragma unroll
        for (int it = 0; it < 4; it++) {
            int idx4 = tid + it * 256;        // 0..1023
            int row = idx4 >> 4, c4 = idx4 & 15;
            int base = row * HST + c4 * 4;
            // K: [key][d]
            float4 kv = ((const float4*)Kg)[idx4];
            __half h0, l0, h1, l1, h2, l2, h3, l3;
            split2_fp16(kv.x, h0, l0); split2_fp16(kv.y, h1, l1);
            split2_fp16(kv.z, h2, l2); split2_fp16(kv.w, h3, l3);
            *(__half2*)&KH[base] = __halves2half2(h0, h1);
            *(__half2*)&KH[base + 2] = __halves2half2(h2, h3);
            *(__half2*)&KL[base] = __halves2half2(l0, l1);
            *(__half2*)&KL[base + 2] = __halves2half2(l2, l3);
            // V: d-major [d][key] via g_vt
            float4 vv = *(const float4*)(VTg + (size_t)row * cT + c4 * 4);
            split2_fp16(vv.x, h0, l0); split2_fp16(vv.y, h1, l1);
            split2_fp16(vv.z, h2, l2); split2_fp16(vv.w, h3, l3);
            *(__half2*)&VH[base] = __halves2half2(h0, h1);
            *(__half2*)&VH[base + 2] = __halves2half2(h2, h3);
            *(__half2*)&VL[base] = __halves2half2(l0, l1);
            *(__half2*)&VL[base + 2] = __halves2half2(l2, l3);
        }
        __syncthreads();

        const bool active = (kt * 64 <= qt * 128 + m0 + 15);
        if (active) {
            // ---- S = Q K^T (3-MMA fp16 2-plane) ----
            float s[8][4];
#pragma unroll
            for (int nt = 0; nt < 8; nt++)
#pragma unroll
                for (int c = 0; c < 4; c++) s[nt][c] = 0.f;

#pragma unroll
            for (int kcp = 0; kcp < 4; kcp++) {
                const int kB = kcp * 32;     // 16 halves per k-step
                uint32_t aH[4], aL[4];
                ldsm4(qhB + 2u * ((m0 + aRow) * HST) + kB + aColB, aH);
                ldsm4(qlB + 2u * ((m0 + aRow) * HST) + kB + aColB, aL);
                uint32_t bfh[8][2], bfl[8][2];
#pragma unroll
                for (int np = 0; np < 4; np++) {
                    uint32_t t4[4];
                    ldsm4(khB + 2u * ((np * 16 + bRow) * HST) + kB + bColB, t4);
                    bfh[2 * np][0] = t4[0]; bfh[2 * np][1] = t4[1];
                    bfh[2 * np + 1][0] = t4[2]; bfh[2 * np + 1][1] = t4[3];
                    ldsm4(klB + 2u * ((np * 16 + bRow) * HST) + kB + bColB, t4);
                    bfl[2 * np][0] = t4[0]; bfl[2 * np][1] = t4[1];
                    bfl[2 * np + 1][0] = t4[2]; bfl[2 * np + 1][1] = t4[3];
                }
#pragma unroll
                for (int nt = 0; nt < 8; nt++) {
                    mma_f16(s[nt], aL, bfh[nt]);      // Ql.Kh
                    mma_f16(s[nt], aH, bfl[nt]);      // Qh.Kl
                    mma_f16(s[nt], aH, bfh[nt]);      // Qh.Kh
                }
            }

            // ---- causal mask ----
            if (kt >= 2 * qt) {
                int q0 = qt * 128 + m0 + g, q1 = q0 + 8;
#pragma unroll
                for (int nt = 0; nt < 8; nt++) {
                    int kc0 = kt * 64 + nt * 8 + 2 * l4;
                    if (kc0 > q0) s[nt][0] = -1e30f;
                    if (kc0 + 1 > q0) s[nt][1] = -1e30f;
                    if (kc0 > q1) s[nt][2] = -1e30f;
                    if (kc0 + 1 > q1) s[nt][3] = -1e30f;
                }
            }

            // ---- online softmax ----
#pragma unroll
            for (int r = 0; r < 2; r++) {
                float rm = -1e30f;
#pragma unroll
                for (int nt = 0; nt < 8; nt++)
                    rm = fmaxf(rm, fmaxf(s[nt][2 * r], s[nt][2 * r + 1]));
                rm = fmaxf(rm, __shfl_xor_sync(0xffffffffu, rm, 1));
                rm = fmaxf(rm, __shfl_xor_sync(0xffffffffu, rm, 2));
                float mnew = fmaxf(m_i[r], rm);
                float alpha = __expf(m_i[r] - mnew);
                float rs = 0.f;
#pragma unroll
                for (int nt = 0; nt < 8; nt++) {
                    s[nt][2 * r] = __expf(s[nt][2 * r] - mnew);
                    s[nt][2 * r + 1] = __expf(s[nt][2 * r + 1] - mnew);
                    rs += s[nt][2 * r] + s[nt][2 * r + 1];
                }
                rs += __shfl_xor_sync(0xffffffffu, rs, 1);
                rs += __shfl_xor_sync(0xffffffffu, rs, 2);
                l_i[r] = l_i[r] * alpha + rs;
                m_i[r] = mnew;
#pragma unroll
                for (int nt = 0; nt < 8; nt++) {
                    O[nt][2 * r] *= alpha;
                    O[nt][2 * r + 1] *= alpha;
                }
            }

            // ---- stage P (fp16 hi/lo) ----
#pragma unroll
            for (int nt = 0; nt < 8; nt++) {
                int col = nt * 8 + 2 * l4;
                __half h0, l0, h1, l1;
                split2_fp16(s[nt][0], h0, l0); split2_fp16(s[nt][1], h1, l1);
                *(__half2*)&PH[(m0 + g) * HST + col] = __halves2half2(h0, h1);
                *(__half2*)&PL[(m0 + g) * HST + col] = __halves2half2(l0, l1);
                split2_fp16(s[nt][2], h0, l0); split2_fp16(s[nt][3], h1, l1);
                *(__half2*)&PH[(m0 + g + 8) * HST + col] = __halves2half2(h0, h1);
                *(__half2*)&PL[(m0 + g + 8) * HST + col] = __halves2half2(l0, l1);
            }
            __syncwarp();   // P rows are warp-private

            // ---- O += P V ----
#pragma unroll
            for (int kcp = 0; kcp < 4; kcp++) {
                const int kB = kcp * 32;
                uint32_t pH[4], pL[4];
                ldsm4(phB + 2u * ((m0 + aRow) * HST) + kB + aColB, pH);
                ldsm4(plB + 2u * ((m0 + aRow) * HST) + kB + aColB, pL);
#pragma unroll
                for (int np = 0; np < 4; np++) {
                    uint32_t th[4], tl[4];
                    ldsm4(vhB + 2u * ((np * 16 + bRow) * HST) + kB + bColB, th);
                    ldsm4(vlB + 2u * ((np * 16 + bRow) * HST) + kB + bColB, tl);
                    uint32_t vh0[2] = {th[0], th[1]}, vh1[2] = {th[2], th[3]};
                    uint32_t vl0[2] = {tl[0], tl[1]}, vl1[2] = {tl[2], tl[3]};
                    mma_f16(O[2 * np], pL, vh0);          // Pl.Vh
                    mma_f16(O[2 * np], pH, vl0);          // Ph.Vl
                    mma_f16(O[2 * np], pH, vh0);          // Ph.Vh
                    mma_f16(O[2 * np + 1], pL, vh1);
                    mma_f16(O[2 * np + 1], pH, vl1);
                    mma_f16(O[2 * np + 1], pH, vh1);
                }
            }
        }
    }

    // ---- epilogue -> 2 fp16 planes for the output projection ----
    int b = bh >> 4, h = bh & 15;
    float inv0 = 1.0f / l_i[0], inv1 = 1.0f / l_i[1];
    int q0 = qt * 128 + m0 + g;
    size_t row0 = (size_t)(b * cT) + q0;
#pragma unroll
    for (int nt = 0; nt < 8; nt++) {
        int d = h * 64 + nt * 8 + 2 * l4;
        __half h0, l0, h1, l1;
        split2_fp16(O[nt][0] * inv0, h0, l0);
        split2_fp16(O[nt][1] * inv0, h1, l1);
        *(__half2*)&g_ah[row0 * cC + d] = __halves2half2(h0, h1);
        *(__half2*)&g_al[row0 * cC + d] = __halves2half2(l0, l1);
        split2_fp16(O[nt][2] * inv1, h0, l0);
        split2_fp16(O[nt][3] * inv1, h1, l1);
        *(__half2*)&g_ah[(row0 + 8) * cC + d] = __halves2half2(h0, h1);
        *(__half2*)&g_al[(row0 + 8) * cC + d] = __halves2half2(l0, l1);
    }
}

// -------------------- launch --------------------
extern "C" void kernel_launch(void* const* d_in, const int* in_sizes, int n_in,
                              void* d_out, int out_size) {
    (void)in_sizes; (void)n_in; (void)out_size;
    const float* x = (const float*)d_in[0];
    const float* w_qkv = (const float*)d_in[1];
    const float* w_out = (const float*)d_in[2];
    float* out = (float*)d_out;

    abssum_partial_kernel<<<1024, 256>>>(w_qkv, cNWq);
    finalize_scale_kernel<<<1, 256>>>(1.0f / (float)cNWq);
    quantize_kernel<0><<<cNWq / 4 / 256, 256>>>(w_qkv, cNWq / 4);
    abssum_partial_kernel<<<1024, 256>>>(w_out, cNWo);
    finalize_scale_kernel<<<1, 256>>>(1.0f / (float)cNWo);
    quantize_kernel<1><<<cNWo / 4 / 256, 256>>>(w_out, cNWo / 4);

    split_x_kernel<<<cM * cK / 4 / 256, 256>>>(x);

    // qkv projection (fp16 2-plane)
    {
        cudaFuncSetAttribute(gemm_fp16_kernel<0>,
                             cudaFuncAttributeMaxDynamicSharedMemorySize, GEMM_SMEM_BYTES);
        dim3 grid(cNqkv / 128, cM / 128);
        gemm_fp16_kernel<0><<<grid, 256, GEMM_SMEM_BYTES>>>(nullptr);
    }

    // V transpose
    {
        dim3 grid(cT / 32, cD / 32, cB * cH);
        transpose_v_kernel<<<grid, dim3(32, 8)>>>();
    }

    // fp16 tensor-core causal flash attention
    {
        cudaFuncSetAttribute(flash_attn_f16_kernel,
                             cudaFuncAttributeMaxDynamicSharedMemorySize, ATTN_SMEM);
        dim3 grid(cT / 128, cB * cH);
        flash_attn_f16_kernel<<<grid, 256, ATTN_SMEM>>>();
    }

    // output projection (fp16 2-plane)
    {
        cudaFuncSetAttribute(gemm_fp16_kernel<1>,
                             cudaFuncAttributeMaxDynamicSharedMemorySize, GEMM_SMEM_BYTES);
        dim3 grid(cC / 128, cM / 128);
        gemm_fp16_kernel<1><<<grid, 256, GEMM_SMEM_BYTES>>>(out);
    }
}